// round 8
// baseline (speedup 1.0000x reference)
#include <cuda_runtime.h>
#include <cstdint>

#define DM   1024
#define SEQ  2048
#define BATCH 4
#define NH   16
#define DH   64

// Scratch (allocation-free)
__device__ float g_Q[BATCH * NH * SEQ * DH];   // [B,H,S,Dh], pre-scaled by Dh^-0.5
__device__ float g_K[BATCH * NH * SEQ * DH];
__device__ float g_V[BATCH * NH * SEQ * DH];
__device__ float g_O[BATCH * SEQ * DM];        // [B,S,D]

// ============================================================================
// Helpers
// ============================================================================
__device__ __forceinline__ uint32_t f2tf32(float x) {
    uint32_t u;
    asm("cvt.rna.tf32.f32 %0, %1;" : "=r"(u) : "f"(x));
    return u;
}
__device__ __forceinline__ uint32_t smem_u32(const void* p) {
    uint32_t a;
    asm("{ .reg .u64 t; cvta.to.shared.u64 t, %1; cvt.u32.u64 %0, t; }" : "=r"(a) : "l"(p));
    return a;
}

#define MMA_TF32(d, a, b0v, b1v)                                               \
    asm volatile("mma.sync.aligned.m16n8k8.row.col.f32.tf32.tf32.f32 "         \
                 "{%0,%1,%2,%3}, {%4,%5,%6,%7}, {%8,%9}, {%0,%1,%2,%3};"       \
                 : "+f"((d)[0]), "+f"((d)[1]), "+f"((d)[2]), "+f"((d)[3])      \
                 : "r"((a)[0]), "r"((a)[1]), "r"((a)[2]), "r"((a)[3]),         \
                   "r"(b0v), "r"(b1v))

#define LDSM_X4(d, addr)                                                       \
    asm volatile("ldmatrix.sync.aligned.m8n8.x4.shared.b16 {%0,%1,%2,%3}, [%4];" \
                 : "=r"((d)[0]), "=r"((d)[1]), "=r"((d)[2]), "=r"((d)[3])      \
                 : "r"(addr))

#define CP_ASYNC16(saddr, gptr)                                                \
    asm volatile("cp.async.cg.shared.global [%0], [%1], 16;"                   \
                 :: "r"(saddr), "l"(gptr))
#define CP_COMMIT() asm volatile("cp.async.commit_group;" ::: "memory")
#define CP_WAIT1()  asm volatile("cp.async.wait_group 1;" ::: "memory")

#define SST 20
#define STAGE_WORDS (2 * 2560)               // A tile + W tile per stage
#define STAGE_BYTES (STAGE_WORDS * 4)
#define GEMM_SMEM_BYTES (3 * STAGE_BYTES)    // 3 stages = 60 KB -> 3 CTAs/SM

// ============================================================================
// GEMM mainloop: CTA 128x128, 128 threads / 4 warps, warp tile 64x64.
// cp.async 3-stage; smem raw fp32; cvt post-ldmatrix.
// ============================================================================
__device__ __forceinline__ void gemm_mainloop_cp(const float* __restrict__ Ablk,
                                                 const float* __restrict__ Wblk,
                                                 uint32_t* smg,
                                                 float (*acc)[8][4],
                                                 int tid) {
    const int lane = tid & 31;
    const int wid = tid >> 5;
    const int wm = (wid & 1) << 6;
    const int wn = (wid >> 1) << 6;
    const int mat = lane >> 3, lrow = lane & 7;
    const int a_row = wm + ((mat & 1) << 3) + lrow;
    const int a_col = (mat >> 1) << 2;
    const int b_row = wn + ((mat >> 1) << 3) + lrow;
    const int b_col = (mat & 1) << 2;
    const uint32_t smb = smem_u32(smg);

    const int ld_r = tid >> 2;        // 0..31 (+32*it)
    const int ld_f = (tid & 3) << 2;  // word offset 0,4,8,12

#pragma unroll
    for (int mt = 0; mt < 4; mt++)
#pragma unroll
        for (int nt = 0; nt < 8; nt++)
#pragma unroll
            for (int e = 0; e < 4; e++) acc[mt][nt][e] = 0.0f;

    // prologue: issue stages 0..1
#pragma unroll
    for (int s = 0; s < 2; s++) {
        const uint32_t dst = smb + (uint32_t)s * STAGE_BYTES;
        const float* a = Ablk + s * 16;
        const float* w = Wblk + s * 16;
#pragma unroll
        for (int it = 0; it < 4; it++) {
            const int row = it * 32 + ld_r;
            const uint32_t so = dst + (uint32_t)((row * SST + ld_f) * 4);
            CP_ASYNC16(so, a + (size_t)row * DM + ld_f);
            CP_ASYNC16(so + 2560 * 4, w + (size_t)row * DM + ld_f);
        }
        CP_COMMIT();
    }

#pragma unroll 1
    for (int c = 0; c < 64; c++) {
        CP_WAIT1();                 // stage c resident
        __syncthreads();            // all threads past compute c-1
        // issue stage c+2 (overwrites buffer consumed at iter c-1)
        if (c + 2 < 64) {
            const int s = (c + 2) % 3;
            const uint32_t dst = smb + (uint32_t)s * STAGE_BYTES;
            const float* a = Ablk + (c + 2) * 16;
            const float* w = Wblk + (c + 2) * 16;
#pragma unroll
            for (int it = 0; it < 4; it++) {
                const int row = it * 32 + ld_r;
                const uint32_t so = dst + (uint32_t)((row * SST + ld_f) * 4);
                CP_ASYNC16(so, a + (size_t)row * DM + ld_f);
                CP_ASYNC16(so + 2560 * 4, w + (size_t)row * DM + ld_f);
            }
        }
        CP_COMMIT();

        const uint32_t asb = smb + (uint32_t)(c % 3) * STAGE_BYTES;
        const uint32_t wsb = asb + 2560 * 4;
#pragma unroll
        for (int k0 = 0; k0 < 16; k0 += 8) {
            uint32_t af[4][4], bf[4][4];
#pragma unroll
            for (int mt = 0; mt < 4; mt++)
                LDSM_X4(af[mt], asb + (uint32_t)(((a_row + mt * 16) * SST + k0 + a_col) * 4));
#pragma unroll
            for (int p = 0; p < 4; p++)
                LDSM_X4(bf[p], wsb + (uint32_t)(((b_row + p * 16) * SST + k0 + b_col) * 4));
#pragma unroll
            for (int mt = 0; mt < 4; mt++)
#pragma unroll
                for (int e = 0; e < 4; e++)
                    af[mt][e] = f2tf32(__uint_as_float(af[mt][e]));
#pragma unroll
            for (int p = 0; p < 4; p++)
#pragma unroll
                for (int e = 0; e < 4; e++)
                    bf[p][e] = f2tf32(__uint_as_float(bf[p][e]));
#pragma unroll
            for (int nt = 0; nt < 8; nt++) {
                const uint32_t b0 = bf[nt >> 1][(nt & 1) << 1];
                const uint32_t b1 = bf[nt >> 1][((nt & 1) << 1) + 1];
#pragma unroll
                for (int mt = 0; mt < 4; mt++)
                    MMA_TF32(acc[mt][nt], af[mt], b0, b1);
            }
        }
    }
}

__global__ void __launch_bounds__(128, 3) qkv_gemm_mma(const float* __restrict__ Xq,
                                                       const float* __restrict__ Xkv,
                                                       const float* __restrict__ Wq,
                                                       const float* __restrict__ Wk,
                                                       const float* __restrict__ Wv) {
    extern __shared__ uint32_t smg[];
    const int bz = blockIdx.z;
    const float* A = (bz == 0) ? Xq : Xkv;
    const float* W = (bz == 0) ? Wq : ((bz == 1) ? Wk : Wv);
    float* out     = (bz == 0) ? g_Q : ((bz == 1) ? g_K : g_V);
    const float scale = (bz == 0) ? 0.125f : 1.0f;

    const int m0 = blockIdx.y * 128;
    const int n0 = blockIdx.x * 128;
    const int tid = threadIdx.x;
    const int lane = tid & 31, wid = tid >> 5;
    const int wm = (wid & 1) << 6, wn = (wid >> 1) << 6;
    const int r = lane >> 2, cl = lane & 3;

    float acc[4][8][4];
    gemm_mainloop_cp(A + (size_t)m0 * DM, W + (size_t)n0 * DM, smg, acc, tid);

#pragma unroll
    for (int mt = 0; mt < 4; mt++) {
#pragma unroll
        for (int nt = 0; nt < 8; nt++) {
            const int mr = m0 + wm + mt * 16 + r;
            const int nc = n0 + wn + nt * 8 + 2 * cl;
            const int b = mr >> 11, s = mr & 2047;
            const int h = nc >> 6, dh = nc & 63;
            float* p0 = out + (((size_t)(b * NH + h) * SEQ + s) * DH + dh);
            *(float2*)p0 = make_float2(acc[mt][nt][0] * scale, acc[mt][nt][1] * scale);
            float* p1 = out + (((size_t)(b * NH + h) * SEQ + (s + 8)) * DH + dh);
            *(float2*)p1 = make_float2(acc[mt][nt][2] * scale, acc[mt][nt][3] * scale);
        }
    }
}

__global__ void __launch_bounds__(128, 3) proj_gemm_mma(const float* __restrict__ Wo,
                                                        float* __restrict__ C) {
    extern __shared__ uint32_t smg[];
    const int m0 = blockIdx.y * 128;
    const int n0 = blockIdx.x * 128;
    const int tid = threadIdx.x;
    const int lane = tid & 31, wid = tid >> 5;
    const int wm = (wid & 1) << 6, wn = (wid >> 1) << 6;
    const int r = lane >> 2, cl = lane & 3;

    float acc[4][8][4];
    gemm_mainloop_cp(g_O + (size_t)m0 * DM, Wo + (size_t)n0 * DM, smg, acc, tid);

#pragma unroll
    for (int mt = 0; mt < 4; mt++) {
#pragma unroll
        for (int nt = 0; nt < 8; nt++) {
            const int mr = m0 + wm + mt * 16 + r;
            const int nc = n0 + wn + nt * 8 + 2 * cl;
            *(float2*)&C[(size_t)mr * DM + nc] = make_float2(acc[mt][nt][0], acc[mt][nt][1]);
            *(float2*)&C[(size_t)(mr + 8) * DM + nc] = make_float2(acc[mt][nt][2], acc[mt][nt][3]);
        }
    }
}

// ============================================================================
// Flash attention, tf32 mma + ldmatrix; K/V register-staged (prefetched one
// tile ahead so LDG latency hides under MMA work).
// BQ=128, BK=64, Dh=64, 256 threads (8 warps x 16 q-rows each).
// ============================================================================
#define AST 68
#define OFF_Q 0
#define OFF_K (128 * AST)
#define OFF_V (192 * AST)
#define OFF_P (256 * AST)
#define ATTN_SMEM_BYTES (384 * AST * 4)

__global__ void __launch_bounds__(256, 2) attn_mma() {
    extern __shared__ uint32_t sm4[];
    uint32_t* Qs = sm4 + OFF_Q;
    uint32_t* Ks = sm4 + OFF_K;
    uint32_t* Vs = sm4 + OFF_V;
    uint32_t* Ps = sm4 + OFF_P;

    const int tid = threadIdx.x;
    const int wid = tid >> 5, lane = tid & 31;
    const int r = lane >> 2, cl = lane & 3;
    const int mat = lane >> 3, lrow = lane & 7;
    const int qt = (int)(gridDim.x - 1) - (int)blockIdx.x;   // heavy first
    const int bh = blockIdx.y;
    const int q0 = qt * 128;
    const int wq = wid * 16;
    const size_t base = (size_t)bh * SEQ * DH;

    const uint32_t Qs_b = smem_u32(Qs), Ks_b = smem_u32(Ks);
    const uint32_t Vs_b = smem_u32(Vs), Ps_b = smem_u32(Ps);
    const int a_off = ((mat & 1) << 3) + lrow;
    const int a_col = (mat >> 1) << 2;
    const int b_off = ((mat >> 1) << 3) + lrow;
    const int b_col = (mat & 1) << 2;

    // K loader mapping: 4 rows/thread; V loader: 4 float4 of one row, transposed
    const int kc = tid >> 4;               // base row 0..15 (+16*it)
    const int kf = (tid & 15) << 2;        // col 0..60
    const int vc = tid & 63;
    const int vdg = (tid >> 6) << 4;

    // Load Q tile (128 x 64) as tf32
#pragma unroll
    for (int it = 0; it < 8; it++) {
        const int id = it * 256 + tid;
        const int row = id >> 4, f4 = (id & 15) << 2;
        float4 v = *(const float4*)&g_Q[base + (size_t)(q0 + row) * DH + f4];
        uint4 t = make_uint4(f2tf32(v.x), f2tf32(v.y), f2tf32(v.z), f2tf32(v.w));
        *(uint4*)&Qs[row * AST + f4] = t;
    }

    float o[8][4];
#pragma unroll
    for (int nf = 0; nf < 8; nf++)
#pragma unroll
        for (int e = 0; e < 4; e++) o[nf][e] = 0.0f;
    float m0v = -1e30f, m1v = -1e30f, l0v = 0.0f, l1v = 0.0f;

    // Prefetch K/V for tile 0 into registers
    float4 kr[4], vr[4];
#pragma unroll
    for (int it = 0; it < 4; it++)
        kr[it] = *(const float4*)&g_K[base + (size_t)(it * 16 + kc) * DH + kf];
#pragma unroll
    for (int i = 0; i < 4; i++)
        vr[i] = *(const float4*)&g_V[base + (size_t)vc * DH + vdg + i * 4];

    const int ntiles = 2 * qt + 2;
    for (int t = 0; t < ntiles; t++) {
        __syncthreads();      // prev tile's MMAs done reading Ks/Vs
        // Store staged K (row-major tf32) and V (transposed tf32)
#pragma unroll
        for (int it = 0; it < 4; it++) {
            uint4 tt = make_uint4(f2tf32(kr[it].x), f2tf32(kr[it].y),
                                  f2tf32(kr[it].z), f2tf32(kr[it].w));
            *(uint4*)&Ks[(it * 16 + kc) * AST + kf] = tt;
        }
#pragma unroll
        for (int i = 0; i < 4; i++) {
            Vs[(vdg + i * 4 + 0) * AST + vc] = f2tf32(vr[i].x);
            Vs[(vdg + i * 4 + 1) * AST + vc] = f2tf32(vr[i].y);
            Vs[(vdg + i * 4 + 2) * AST + vc] = f2tf32(vr[i].z);
            Vs[(vdg + i * 4 + 3) * AST + vc] = f2tf32(vr[i].w);
        }
        __syncthreads();

        // Prefetch next tile's K/V (latency hidden under this tile's compute)
        if (t + 1 < ntiles) {
            const int kn = (t + 1) * 64;
#pragma unroll
            for (int it = 0; it < 4; it++)
                kr[it] = *(const float4*)&g_K[base + (size_t)(kn + it * 16 + kc) * DH + kf];
#pragma unroll
            for (int i = 0; i < 4; i++)
                vr[i] = *(const float4*)&g_V[base + (size_t)(kn + vc) * DH + vdg + i * 4];
        }

        const int k0g = t * 64;

        // Scores: S[16 x 64] per warp
        float sfr[8][4];
#pragma unroll
        for (int nf = 0; nf < 8; nf++)
#pragma unroll
            for (int e = 0; e < 4; e++) sfr[nf][e] = 0.0f;
#pragma unroll
        for (int k = 0; k < 8; k++) {
            const int k0 = k * 8;
            uint32_t af[4], bf[4][4];
            LDSM_X4(af, Qs_b + (uint32_t)(((wq + a_off) * AST + k0 + a_col) * 4));
#pragma unroll
            for (int p = 0; p < 4; p++)
                LDSM_X4(bf[p], Ks_b + (uint32_t)(((p * 16 + b_off) * AST + k0 + b_col) * 4));
#pragma unroll
            for (int nf = 0; nf < 8; nf++)
                MMA_TF32(sfr[nf], af, bf[nf >> 1][(nf & 1) << 1], bf[nf >> 1][((nf & 1) << 1) + 1]);
        }

        if (t >= 2 * qt) {
            const int row0 = q0 + wq + r, row1 = row0 + 8;
#pragma unroll
            for (int nf = 0; nf < 8; nf++) {
                const int c0 = k0g + nf * 8 + 2 * cl;
                if (c0 > row0) sfr[nf][0] = -1e30f;
                if (c0 + 1 > row0) sfr[nf][1] = -1e30f;
                if (c0 > row1) sfr[nf][2] = -1e30f;
                if (c0 + 1 > row1) sfr[nf][3] = -1e30f;
            }
        }

        float mx0 = -1e30f, mx1 = -1e30f;
#pragma unroll
        for (int nf = 0; nf < 8; nf++) {
            mx0 = fmaxf(mx0, fmaxf(sfr[nf][0], sfr[nf][1]));
            mx1 = fmaxf(mx1, fmaxf(sfr[nf][2], sfr[nf][3]));
        }
        mx0 = fmaxf(mx0, __shfl_xor_sync(0xffffffffu, mx0, 1));
        mx0 = fmaxf(mx0, __shfl_xor_sync(0xffffffffu, mx0, 2));
        mx1 = fmaxf(mx1, __shfl_xor_sync(0xffffffffu, mx1, 1));
        mx1 = fmaxf(mx1, __shfl_xor_sync(0xffffffffu, mx1, 2));
        const float mn0 = fmaxf(m0v, mx0), mn1 = fmaxf(m1v, mx1);
        const float a0 = __expf(m0v - mn0), a1 = __expf(m1v - mn1);
        float rs0 = 0.0f, rs1 = 0.0f;
        uint32_t* pb0 = Ps + (wq + r) * AST + 2 * cl;
        uint32_t* pb1 = pb0 + 8 * AST;
#pragma unroll
        for (int nf = 0; nf < 8; nf++) {
            const float p0 = __expf(sfr[nf][0] - mn0);
            const float p1 = __expf(sfr[nf][1] - mn0);
            const float p2 = __expf(sfr[nf][2] - mn1);
            const float p3 = __expf(sfr[nf][3] - mn1);
            rs0 += p0 + p1;
            rs1 += p2 + p3;
            pb0[nf * 8 + 0] = f2tf32(p0);
            pb0[nf * 8 + 1] = f2tf32(p1);
            pb1[nf * 8 + 0] = f2tf32(p2);
            pb1[nf * 8 + 1] = f2tf32(p3);
        }
        rs0 += __shfl_xor_sync(0xffffffffu, rs0, 1);
        rs0 += __shfl_xor_sync(0xffffffffu, rs0, 2);
        rs1 += __shfl_xor_sync(0xffffffffu, rs1, 1);
        rs1 += __shfl_xor_sync(0xffffffffu, rs1, 2);
        l0v = l0v * a0 + rs0;
        l1v = l1v * a1 + rs1;
        m0v = mn0;
        m1v = mn1;
#pragma unroll
        for (int nf = 0; nf < 8; nf++) {
            o[nf][0] *= a0;
            o[nf][1] *= a0;
            o[nf][2] *= a1;
            o[nf][3] *= a1;
        }
        __syncwarp();

        // O += P(16x64) . V(64x64)
#pragma unroll
        for (int k = 0; k < 8; k++) {
            const int k0 = k * 8;
            uint32_t af[4], bf[4][4];
            LDSM_X4(af, Ps_b + (uint32_t)(((wq + a_off) * AST + k0 + a_col) * 4));
#pragma unroll
            for (int p = 0; p < 4; p++)
                LDSM_X4(bf[p], Vs_b + (uint32_t)(((p * 16 + b_off) * AST + k0 + b_col) * 4));
#pragma unroll
            for (int nf = 0; nf < 8; nf++)
                MMA_TF32(o[nf], af, bf[nf >> 1][(nf & 1) << 1], bf[nf >> 1][((nf & 1) << 1) + 1]);
        }
    }

    const float i0 = 1.0f / l0v, i1 = 1.0f / l1v;
    const int b = bh >> 4, h = bh & 15;
    const int row0 = q0 + wq + r, row1 = row0 + 8;
#pragma unroll
    for (int nf = 0; nf < 8; nf++) {
        const int col = h * DH + nf * 8 + 2 * cl;
        *(float2*)&g_O[(size_t)(b * SEQ + row0) * DM + col] =
            make_float2(o[nf][0] * i0, o[nf][1] * i0);
        *(float2*)&g_O[(size_t)(b * SEQ + row1) * DM + col] =
            make_float2(o[nf][2] * i1, o[nf][3] * i1);
    }
}

// ============================================================================
// Launch
// ============================================================================
extern "C" void kernel_launch(void* const* d_in, const int* in_sizes, int n_in,
                              void* d_out, int out_size) {
    const float* q  = (const float*)d_in[0];
    const float* kv = (const float*)d_in[1];
    const float* Wq = (const float*)d_in[2];
    const float* Wk = (const float*)d_in[3];
    const float* Wv = (const float*)d_in[4];
    const float* Wo = (const float*)d_in[5];
    float* out = (float*)d_out;

    cudaFuncSetAttribute(qkv_gemm_mma, cudaFuncAttributeMaxDynamicSharedMemorySize,
                         GEMM_SMEM_BYTES);
    cudaFuncSetAttribute(proj_gemm_mma, cudaFuncAttributeMaxDynamicSharedMemorySize,
                         GEMM_SMEM_BYTES);
    cudaFuncSetAttribute(attn_mma, cudaFuncAttributeMaxDynamicSharedMemorySize,
                         ATTN_SMEM_BYTES);

    qkv_gemm_mma<<<dim3(DM / 128, (BATCH * SEQ) / 128, 3), 128, GEMM_SMEM_BYTES>>>(q, kv, Wq, Wk, Wv);
    attn_mma<<<dim3(SEQ / 128, BATCH * NH), 256, ATTN_SMEM_BYTES>>>();
    proj_gemm_mma<<<dim3(DM / 128, (BATCH * SEQ) / 128), 128, GEMM_SMEM_BYTES>>>(Wo, out);
}

// round 9
// speedup vs baseline: 1.5031x; 1.5031x over previous
#include <cuda_runtime.h>
#include <cstdint>

#define DM   1024
#define SEQ  2048
#define BATCH 4
#define NH   16
#define DH   64

// Scratch (allocation-free)
__device__ float g_Q[BATCH * NH * SEQ * DH];   // [B,H,S,Dh], tf32-rounded, pre-scaled
__device__ float g_K[BATCH * NH * SEQ * DH];   // tf32-rounded
__device__ float g_V[BATCH * NH * SEQ * DH];   // tf32-rounded
__device__ float g_O[BATCH * SEQ * DM];        // [B,S,D]

// ============================================================================
// Helpers
// ============================================================================
__device__ __forceinline__ uint32_t f2tf32(float x) {
    uint32_t u;
    asm("cvt.rna.tf32.f32 %0, %1;" : "=r"(u) : "f"(x));
    return u;
}
__device__ __forceinline__ uint32_t smem_u32(const void* p) {
    uint32_t a;
    asm("{ .reg .u64 t; cvta.to.shared.u64 t, %1; cvt.u32.u64 %0, t; }" : "=r"(a) : "l"(p));
    return a;
}

#define MMA_TF32(d, a, b0v, b1v)                                               \
    asm volatile("mma.sync.aligned.m16n8k8.row.col.f32.tf32.tf32.f32 "         \
                 "{%0,%1,%2,%3}, {%4,%5,%6,%7}, {%8,%9}, {%0,%1,%2,%3};"       \
                 : "+f"((d)[0]), "+f"((d)[1]), "+f"((d)[2]), "+f"((d)[3])      \
                 : "r"((a)[0]), "r"((a)[1]), "r"((a)[2]), "r"((a)[3]),         \
                   "r"(b0v), "r"(b1v))

#define LDSM_X4(d, addr)                                                       \
    asm volatile("ldmatrix.sync.aligned.m8n8.x4.shared.b16 {%0,%1,%2,%3}, [%4];" \
                 : "=r"((d)[0]), "=r"((d)[1]), "=r"((d)[2]), "=r"((d)[3])      \
                 : "r"(addr))

#define SST 20

// ============================================================================
// GEMM mainloop (R5-validated): CTA 128x128, 4 warps, warp tile 64x64.
// Register-staged double-buffered smem (tf32 pre-converted in loader).
// ============================================================================
__device__ __forceinline__ void gemm_mainloop_64(const float* __restrict__ Ablk,
                                                 const float* __restrict__ Wblk,
                                                 uint32_t (*As)[2560],
                                                 uint32_t (*Ws)[2560],
                                                 float (*acc)[8][4],
                                                 int tid) {
    const int lane = tid & 31;
    const int wid = tid >> 5;
    const int wm = (wid & 1) << 6;
    const int wn = (wid >> 1) << 6;
    const int mat = lane >> 3, lrow = lane & 7;
    const int a_row = wm + ((mat & 1) << 3) + lrow;
    const int a_col = (mat >> 1) << 2;
    const int b_row = wn + ((mat >> 1) << 3) + lrow;
    const int b_col = (mat & 1) << 2;
    const uint32_t As_b = smem_u32(As);
    const uint32_t Ws_b = smem_u32(Ws);

#pragma unroll
    for (int mt = 0; mt < 4; mt++)
#pragma unroll
        for (int nt = 0; nt < 8; nt++)
#pragma unroll
            for (int e = 0; e < 4; e++) acc[mt][nt][e] = 0.0f;

    // prologue: chunk 0
#pragma unroll
    for (int it = 0; it < 4; it++) {
        const int id = it * 128 + tid;
        const int row = id >> 2, f4 = id & 3;
        float4 va = *(const float4*)(Ablk + (size_t)row * DM + f4 * 4);
        float4 vw = *(const float4*)(Wblk + (size_t)row * DM + f4 * 4);
        uint4 ta = make_uint4(f2tf32(va.x), f2tf32(va.y), f2tf32(va.z), f2tf32(va.w));
        uint4 tw = make_uint4(f2tf32(vw.x), f2tf32(vw.y), f2tf32(vw.z), f2tf32(vw.w));
        *(uint4*)(&As[0][row * SST + f4 * 4]) = ta;
        *(uint4*)(&Ws[0][row * SST + f4 * 4]) = tw;
    }
    __syncthreads();

    float4 ra[4], rw[4];
#pragma unroll 1
    for (int c = 0; c < 64; c++) {
        const int cur = c & 1;
        if (c + 1 < 64) {
#pragma unroll
            for (int it = 0; it < 4; it++) {
                const int id = it * 128 + tid;
                const int row = id >> 2, f4 = id & 3;
                ra[it] = *(const float4*)(Ablk + (size_t)row * DM + (c + 1) * 16 + f4 * 4);
                rw[it] = *(const float4*)(Wblk + (size_t)row * DM + (c + 1) * 16 + f4 * 4);
            }
        }
        const uint32_t asb = As_b + (uint32_t)cur * (2560 * 4);
        const uint32_t wsb = Ws_b + (uint32_t)cur * (2560 * 4);
#pragma unroll
        for (int k0 = 0; k0 < 16; k0 += 8) {
            uint32_t af[4][4], bf[4][4];
#pragma unroll
            for (int mt = 0; mt < 4; mt++)
                LDSM_X4(af[mt], asb + (uint32_t)(((a_row + mt * 16) * SST + k0 + a_col) * 4));
#pragma unroll
            for (int p = 0; p < 4; p++)
                LDSM_X4(bf[p], wsb + (uint32_t)(((b_row + p * 16) * SST + k0 + b_col) * 4));
#pragma unroll
            for (int nt = 0; nt < 8; nt++) {
                const uint32_t b0 = bf[nt >> 1][(nt & 1) << 1];
                const uint32_t b1 = bf[nt >> 1][((nt & 1) << 1) + 1];
#pragma unroll
                for (int mt = 0; mt < 4; mt++)
                    MMA_TF32(acc[mt][nt], af[mt], b0, b1);
            }
        }
        if (c + 1 < 64) {
            const int nxt = cur ^ 1;
#pragma unroll
            for (int it = 0; it < 4; it++) {
                const int id = it * 128 + tid;
                const int row = id >> 2, f4 = id & 3;
                uint4 ta = make_uint4(f2tf32(ra[it].x), f2tf32(ra[it].y),
                                      f2tf32(ra[it].z), f2tf32(ra[it].w));
                uint4 tw = make_uint4(f2tf32(rw[it].x), f2tf32(rw[it].y),
                                      f2tf32(rw[it].z), f2tf32(rw[it].w));
                *(uint4*)(&As[nxt][row * SST + f4 * 4]) = ta;
                *(uint4*)(&Ws[nxt][row * SST + f4 * 4]) = tw;
            }
            __syncthreads();
        }
    }
}

__global__ void __launch_bounds__(128) qkv_gemm_mma(const float* __restrict__ Xq,
                                                    const float* __restrict__ Xkv,
                                                    const float* __restrict__ Wq,
                                                    const float* __restrict__ Wk,
                                                    const float* __restrict__ Wv) {
    __shared__ uint32_t As[2][2560];
    __shared__ uint32_t Ws[2][2560];
    const int bz = blockIdx.z;
    const float* A = (bz == 0) ? Xq : Xkv;
    const float* W = (bz == 0) ? Wq : ((bz == 1) ? Wk : Wv);
    float* out     = (bz == 0) ? g_Q : ((bz == 1) ? g_K : g_V);
    const float scale = (bz == 0) ? 0.125f : 1.0f;

    const int m0 = blockIdx.y * 128;
    const int n0 = blockIdx.x * 128;
    const int tid = threadIdx.x;
    const int lane = tid & 31, wid = tid >> 5;
    const int wm = (wid & 1) << 6, wn = (wid >> 1) << 6;
    const int r = lane >> 2, cl = lane & 3;

    float acc[4][8][4];
    gemm_mainloop_64(A + (size_t)m0 * DM, W + (size_t)n0 * DM, As, Ws, acc, tid);

    // Epilogue: scatter to [B,H,S,Dh], pre-rounded to tf32 (attn consumes as-is;
    // cvt.rna is idempotent so numerics match the R5 baseline bit-exactly).
#pragma unroll
    for (int mt = 0; mt < 4; mt++) {
#pragma unroll
        for (int nt = 0; nt < 8; nt++) {
            const int mr = m0 + wm + mt * 16 + r;
            const int nc = n0 + wn + nt * 8 + 2 * cl;
            const int b = mr >> 11, s = mr & 2047;
            const int h = nc >> 6, dh = nc & 63;
            float* p0 = out + (((size_t)(b * NH + h) * SEQ + s) * DH + dh);
            *(float2*)p0 = make_float2(__uint_as_float(f2tf32(acc[mt][nt][0] * scale)),
                                       __uint_as_float(f2tf32(acc[mt][nt][1] * scale)));
            float* p1 = out + (((size_t)(b * NH + h) * SEQ + (s + 8)) * DH + dh);
            *(float2*)p1 = make_float2(__uint_as_float(f2tf32(acc[mt][nt][2] * scale)),
                                       __uint_as_float(f2tf32(acc[mt][nt][3] * scale)));
        }
    }
}

__global__ void __launch_bounds__(128) proj_gemm_mma(const float* __restrict__ Wo,
                                                     float* __restrict__ C) {
    __shared__ uint32_t As[2][2560];
    __shared__ uint32_t Ws[2][2560];
    const int m0 = blockIdx.y * 128;
    const int n0 = blockIdx.x * 128;
    const int tid = threadIdx.x;
    const int lane = tid & 31, wid = tid >> 5;
    const int wm = (wid & 1) << 6, wn = (wid >> 1) << 6;
    const int r = lane >> 2, cl = lane & 3;

    float acc[4][8][4];
    gemm_mainloop_64(g_O + (size_t)m0 * DM, Wo + (size_t)n0 * DM, As, Ws, acc, tid);

#pragma unroll
    for (int mt = 0; mt < 4; mt++) {
#pragma unroll
        for (int nt = 0; nt < 8; nt++) {
            const int mr = m0 + wm + mt * 16 + r;
            const int nc = n0 + wn + nt * 8 + 2 * cl;
            *(float2*)&C[(size_t)mr * DM + nc] = make_float2(acc[mt][nt][0], acc[mt][nt][1]);
            *(float2*)&C[(size_t)(mr + 8) * DM + nc] = make_float2(acc[mt][nt][2], acc[mt][nt][3]);
        }
    }
}

// ============================================================================
// Flash attention (R5-validated), tf32 mma + ldmatrix. Q/K/V arrive already
// tf32-rounded -> loaders are raw copies (no cvt).
// BQ=128, BK=64, Dh=64, 256 threads (8 warps x 16 q-rows each).
// ============================================================================
#define AST 68
#define OFF_Q 0
#define OFF_K (128 * AST)
#define OFF_V (192 * AST)
#define OFF_P (256 * AST)
#define ATTN_SMEM_BYTES (384 * AST * 4)

__global__ void __launch_bounds__(256) attn_mma() {
    extern __shared__ uint32_t sm4[];
    uint32_t* Qs = sm4 + OFF_Q;
    uint32_t* Ks = sm4 + OFF_K;
    uint32_t* Vs = sm4 + OFF_V;
    uint32_t* Ps = sm4 + OFF_P;

    const int tid = threadIdx.x;
    const int wid = tid >> 5, lane = tid & 31;
    const int r = lane >> 2, cl = lane & 3;
    const int mat = lane >> 3, lrow = lane & 7;
    const int qt = (int)(gridDim.x - 1) - (int)blockIdx.x;   // heavy first
    const int bh = blockIdx.y;
    const int q0 = qt * 128;
    const int wq = wid * 16;
    const size_t base = (size_t)bh * SEQ * DH;

    const uint32_t Qs_b = smem_u32(Qs), Ks_b = smem_u32(Ks);
    const uint32_t Vs_b = smem_u32(Vs), Ps_b = smem_u32(Ps);
    const int a_off = ((mat & 1) << 3) + lrow;
    const int a_col = (mat >> 1) << 2;
    const int b_off = ((mat >> 1) << 3) + lrow;
    const int b_col = (mat & 1) << 2;

    // Load Q tile (128 x 64), already tf32-rounded -> raw copy
    const uint32_t* gQ = (const uint32_t*)g_Q;
#pragma unroll
    for (int it = 0; it < 8; it++) {
        const int id = it * 256 + tid;
        const int row = id >> 4, f4 = (id & 15) << 2;
        uint4 v = *(const uint4*)&gQ[base + (size_t)(q0 + row) * DH + f4];
        *(uint4*)&Qs[row * AST + f4] = v;
    }

    float o[8][4];
#pragma unroll
    for (int nf = 0; nf < 8; nf++)
#pragma unroll
        for (int e = 0; e < 4; e++) o[nf][e] = 0.0f;
    float m0v = -1e30f, m1v = -1e30f, l0v = 0.0f, l1v = 0.0f;

    const int vc = tid & 63;
    const int vdg = (tid >> 6) << 4;
    const uint32_t* gK = (const uint32_t*)g_K;
    const uint32_t* gV = (const uint32_t*)g_V;

    const int ntiles = 2 * qt + 2;
    for (int t = 0; t < ntiles; t++) {
        const int k0g = t * 64;
        __syncthreads();
        // K tile -> Ks[c][d] (raw copy)
#pragma unroll
        for (int it = 0; it < 4; it++) {
            const int id = it * 256 + tid;
            const int c = id >> 4, f4 = (id & 15) << 2;
            uint4 v = *(const uint4*)&gK[base + (size_t)(k0g + c) * DH + f4];
            *(uint4*)&Ks[c * AST + f4] = v;
        }
        // V tile transposed -> Vs[d][c] (raw copy)
#pragma unroll
        for (int i = 0; i < 4; i++) {
            uint4 v = *(const uint4*)&gV[base + (size_t)(k0g + vc) * DH + vdg + i * 4];
            Vs[(vdg + i * 4 + 0) * AST + vc] = v.x;
            Vs[(vdg + i * 4 + 1) * AST + vc] = v.y;
            Vs[(vdg + i * 4 + 2) * AST + vc] = v.z;
            Vs[(vdg + i * 4 + 3) * AST + vc] = v.w;
        }
        __syncthreads();

        // Scores: S[16 x 64] per warp
        float sfr[8][4];
#pragma unroll
        for (int nf = 0; nf < 8; nf++)
#pragma unroll
            for (int e = 0; e < 4; e++) sfr[nf][e] = 0.0f;
#pragma unroll
        for (int k = 0; k < 8; k++) {
            const int k0 = k * 8;
            uint32_t af[4], bf[4][4];
            LDSM_X4(af, Qs_b + (uint32_t)(((wq + a_off) * AST + k0 + a_col) * 4));
#pragma unroll
            for (int p = 0; p < 4; p++)
                LDSM_X4(bf[p], Ks_b + (uint32_t)(((p * 16 + b_off) * AST + k0 + b_col) * 4));
#pragma unroll
            for (int nf = 0; nf < 8; nf++)
                MMA_TF32(sfr[nf], af, bf[nf >> 1][(nf & 1) << 1], bf[nf >> 1][((nf & 1) << 1) + 1]);
        }

        // Causal mask (only diagonal-overlap tiles)
        if (t >= 2 * qt) {
            const int row0 = q0 + wq + r, row1 = row0 + 8;
#pragma unroll
            for (int nf = 0; nf < 8; nf++) {
                const int c0 = k0g + nf * 8 + 2 * cl;
                if (c0 > row0) sfr[nf][0] = -1e30f;
                if (c0 + 1 > row0) sfr[nf][1] = -1e30f;
                if (c0 > row1) sfr[nf][2] = -1e30f;
                if (c0 + 1 > row1) sfr[nf][3] = -1e30f;
            }
        }

        // Online softmax
        float mx0 = -1e30f, mx1 = -1e30f;
#pragma unroll
        for (int nf = 0; nf < 8; nf++) {
            mx0 = fmaxf(mx0, fmaxf(sfr[nf][0], sfr[nf][1]));
            mx1 = fmaxf(mx1, fmaxf(sfr[nf][2], sfr[nf][3]));
        }
        mx0 = fmaxf(mx0, __shfl_xor_sync(0xffffffffu, mx0, 1));
        mx0 = fmaxf(mx0, __shfl_xor_sync(0xffffffffu, mx0, 2));
        mx1 = fmaxf(mx1, __shfl_xor_sync(0xffffffffu, mx1, 1));
        mx1 = fmaxf(mx1, __shfl_xor_sync(0xffffffffu, mx1, 2));
        const float mn0 = fmaxf(m0v, mx0), mn1 = fmaxf(m1v, mx1);
        const float a0 = __expf(m0v - mn0), a1 = __expf(m1v - mn1);
        float rs0 = 0.0f, rs1 = 0.0f;
        uint32_t* pb0 = Ps + (wq + r) * AST + 2 * cl;
        uint32_t* pb1 = pb0 + 8 * AST;
#pragma unroll
        for (int nf = 0; nf < 8; nf++) {
            const float p0 = __expf(sfr[nf][0] - mn0);
            const float p1 = __expf(sfr[nf][1] - mn0);
            const float p2 = __expf(sfr[nf][2] - mn1);
            const float p3 = __expf(sfr[nf][3] - mn1);
            rs0 += p0 + p1;
            rs1 += p2 + p3;
            pb0[nf * 8 + 0] = f2tf32(p0);
            pb0[nf * 8 + 1] = f2tf32(p1);
            pb1[nf * 8 + 0] = f2tf32(p2);
            pb1[nf * 8 + 1] = f2tf32(p3);
        }
        rs0 += __shfl_xor_sync(0xffffffffu, rs0, 1);
        rs0 += __shfl_xor_sync(0xffffffffu, rs0, 2);
        rs1 += __shfl_xor_sync(0xffffffffu, rs1, 1);
        rs1 += __shfl_xor_sync(0xffffffffu, rs1, 2);
        l0v = l0v * a0 + rs0;
        l1v = l1v * a1 + rs1;
        m0v = mn0;
        m1v = mn1;
#pragma unroll
        for (int nf = 0; nf < 8; nf++) {
            o[nf][0] *= a0;
            o[nf][1] *= a0;
            o[nf][2] *= a1;
            o[nf][3] *= a1;
        }
        __syncwarp();

        // O += P(16x64) . V(64x64)
#pragma unroll
        for (int k = 0; k < 8; k++) {
            const int k0 = k * 8;
            uint32_t af[4], bf[4][4];
            LDSM_X4(af, Ps_b + (uint32_t)(((wq + a_off) * AST + k0 + a_col) * 4));
#pragma unroll
            for (int p = 0; p < 4; p++)
                LDSM_X4(bf[p], Vs_b + (uint32_t)(((p * 16 + b_off) * AST + k0 + b_col) * 4));
#pragma unroll
            for (int nf = 0; nf < 8; nf++)
                MMA_TF32(o[nf], af, bf[nf >> 1][(nf & 1) << 1], bf[nf >> 1][((nf & 1) << 1) + 1]);
        }
    }

    // Epilogue
    const float i0 = 1.0f / l0v, i1 = 1.0f / l1v;
    const int b = bh >> 4, h = bh & 15;
    const int row0 = q0 + wq + r, row1 = row0 + 8;
#pragma unroll
    for (int nf = 0; nf < 8; nf++) {
        const int col = h * DH + nf * 8 + 2 * cl;
        *(float2*)&g_O[(size_t)(b * SEQ + row0) * DM + col] =
            make_float2(o[nf][0] * i0, o[nf][1] * i0);
        *(float2*)&g_O[(size_t)(b * SEQ + row1) * DM + col] =
            make_float2(o[nf][2] * i1, o[nf][3] * i1);
    }
}

// ============================================================================
// Launch
// ============================================================================
extern "C" void kernel_launch(void* const* d_in, const int* in_sizes, int n_in,
                              void* d_out, int out_size) {
    const float* q  = (const float*)d_in[0];
    const float* kv = (const float*)d_in[1];
    const float* Wq = (const float*)d_in[2];
    const float* Wk = (const float*)d_in[3];
    const float* Wv = (const float*)d_in[4];
    const float* Wo = (const float*)d_in[5];
    float* out = (float*)d_out;

    cudaFuncSetAttribute(attn_mma, cudaFuncAttributeMaxDynamicSharedMemorySize,
                         ATTN_SMEM_BYTES);

    qkv_gemm_mma<<<dim3(DM / 128, (BATCH * SEQ) / 128, 3), 128>>>(q, kv, Wq, Wk, Wv);
    attn_mma<<<dim3(SEQ / 128, BATCH * NH), 256, ATTN_SMEM_BYTES>>>();
    proj_gemm_mma<<<dim3(DM / 128, (BATCH * SEQ) / 128), 128>>>(Wo, out);
}

// round 10
// speedup vs baseline: 1.6817x; 1.1188x over previous
#include <cuda_runtime.h>
#include <cstdint>

#define DM   1024
#define SEQ  2048
#define BATCH 4
#define NH   16
#define DH   64

// Scratch (allocation-free)
__device__ float g_Q[BATCH * NH * SEQ * DH];   // [B,H,S,Dh], tf32-rounded, pre-scaled
__device__ float g_K[BATCH * NH * SEQ * DH];   // tf32-rounded
__device__ float g_V[BATCH * NH * SEQ * DH];   // tf32-rounded
__device__ float g_O[BATCH * SEQ * DM];        // [B,S,D]

// ============================================================================
// Helpers
// ============================================================================
__device__ __forceinline__ uint32_t f2tf32(float x) {
    uint32_t u;
    asm("cvt.rna.tf32.f32 %0, %1;" : "=r"(u) : "f"(x));
    return u;
}
__device__ __forceinline__ uint32_t smem_u32(const void* p) {
    uint32_t a;
    asm("{ .reg .u64 t; cvta.to.shared.u64 t, %1; cvt.u32.u64 %0, t; }" : "=r"(a) : "l"(p));
    return a;
}

#define MMA_TF32(d, a, b0v, b1v)                                               \
    asm volatile("mma.sync.aligned.m16n8k8.row.col.f32.tf32.tf32.f32 "         \
                 "{%0,%1,%2,%3}, {%4,%5,%6,%7}, {%8,%9}, {%0,%1,%2,%3};"       \
                 : "+f"((d)[0]), "+f"((d)[1]), "+f"((d)[2]), "+f"((d)[3])      \
                 : "r"((a)[0]), "r"((a)[1]), "r"((a)[2]), "r"((a)[3]),         \
                   "r"(b0v), "r"(b1v))

#define LDSM_X4(d, addr)                                                       \
    asm volatile("ldmatrix.sync.aligned.m8n8.x4.shared.b16 {%0,%1,%2,%3}, [%4];" \
                 : "=r"((d)[0]), "=r"((d)[1]), "=r"((d)[2]), "=r"((d)[3])      \
                 : "r"(addr))

#define CP_ASYNC16(saddr, gptr)                                                \
    asm volatile("cp.async.cg.shared.global [%0], [%1], 16;"                   \
                 :: "r"(saddr), "l"(gptr))
#define CP_COMMIT() asm volatile("cp.async.commit_group;" ::: "memory")
#define CP_WAIT1()  asm volatile("cp.async.wait_group 1;" ::: "memory")

// ============================================================================
// GEMM: CTA 128x128, 128 thr / 4 warps, warp tile 64x64, K-chunk 32,
// cp.async 3-stage. Rows are exactly 128B; bank conflicts avoided with
// XOR-chunk swizzle (chunk ^= row&7). smem raw fp32; cvt post-ldmatrix.
// ============================================================================
#define KCH 32
#define HALF_STAGE (128 * KCH * 4)           // 16 KB (one matrix tile)
#define STAGE_BYTES (2 * HALF_STAGE)         // 32 KB (A + W)
#define GEMM_SMEM_BYTES (3 * STAGE_BYTES)    // 96 KB -> 2 CTAs/SM

__device__ __forceinline__ void gemm_issue_stage(const float* __restrict__ Ablk,
                                                 const float* __restrict__ Wblk,
                                                 uint32_t dst, int kbase,
                                                 int lr8, int lch) {
#pragma unroll
    for (int it = 0; it < 8; it++) {
        const int row = it * 16 + lr8;
        const uint32_t off = (uint32_t)(row * 128 + ((lch ^ (row & 7)) << 4));
        CP_ASYNC16(dst + off, Ablk + (size_t)row * DM + kbase + lch * 4);
        CP_ASYNC16(dst + HALF_STAGE + off, Wblk + (size_t)row * DM + kbase + lch * 4);
    }
}

__device__ __forceinline__ void gemm_mainloop_cp32(const float* __restrict__ Ablk,
                                                   const float* __restrict__ Wblk,
                                                   uint32_t* smg,
                                                   float (*acc)[8][4],
                                                   int tid) {
    const int lane = tid & 31;
    const int wid = tid >> 5;
    const int wm = (wid & 1) << 6;
    const int wn = (wid >> 1) << 6;
    const int mat = lane >> 3, lrow = lane & 7;
    const int a_row = wm + ((mat & 1) << 3) + lrow;   // + mt*16
    const int sel_a = mat >> 1;                       // chunk select 0/1
    const int b_row = wn + ((mat >> 1) << 3) + lrow;  // + p*16
    const int sel_b = mat & 1;
    const uint32_t smb = smem_u32(smg);

    const int lr8 = tid >> 3;     // 0..15
    const int lch = tid & 7;      // 16B chunk 0..7

#pragma unroll
    for (int mt = 0; mt < 4; mt++)
#pragma unroll
        for (int nt = 0; nt < 8; nt++)
#pragma unroll
            for (int e = 0; e < 4; e++) acc[mt][nt][e] = 0.0f;

    // prologue: stages 0,1
#pragma unroll
    for (int s = 0; s < 2; s++) {
        gemm_issue_stage(Ablk, Wblk, smb + (uint32_t)s * STAGE_BYTES, s * KCH, lr8, lch);
        CP_COMMIT();
    }

#pragma unroll 1
    for (int c = 0; c < 32; c++) {
        CP_WAIT1();                 // stage c resident (leaves c+1 pending)
        __syncthreads();            // all warps done computing chunk c-1
        if (c + 2 < 32)
            gemm_issue_stage(Ablk, Wblk, smb + (uint32_t)((c + 2) % 3) * STAGE_BYTES,
                             (c + 2) * KCH, lr8, lch);
        CP_COMMIT();

        const uint32_t asb = smb + (uint32_t)(c % 3) * STAGE_BYTES;
        const uint32_t wsb = asb + HALF_STAGE;
#pragma unroll
        for (int kc = 0; kc < 8; kc += 2) {   // k0 = kc*4 in {0,8,16,24}
            uint32_t af[4][4], bf[4][4];
#pragma unroll
            for (int mt = 0; mt < 4; mt++)
                LDSM_X4(af[mt], asb + (uint32_t)((a_row + mt * 16) * 128 +
                                                 (((kc + sel_a) ^ lrow) << 4)));
#pragma unroll
            for (int p = 0; p < 4; p++)
                LDSM_X4(bf[p], wsb + (uint32_t)((b_row + p * 16) * 128 +
                                                (((kc + sel_b) ^ lrow) << 4)));
#pragma unroll
            for (int mt = 0; mt < 4; mt++)
#pragma unroll
                for (int e = 0; e < 4; e++)
                    af[mt][e] = f2tf32(__uint_as_float(af[mt][e]));
#pragma unroll
            for (int p = 0; p < 4; p++)
#pragma unroll
                for (int e = 0; e < 4; e++)
                    bf[p][e] = f2tf32(__uint_as_float(bf[p][e]));
#pragma unroll
            for (int nt = 0; nt < 8; nt++) {
                const uint32_t b0 = bf[nt >> 1][(nt & 1) << 1];
                const uint32_t b1 = bf[nt >> 1][((nt & 1) << 1) + 1];
#pragma unroll
                for (int mt = 0; mt < 4; mt++)
                    MMA_TF32(acc[mt][nt], af[mt], b0, b1);
            }
        }
    }
}

__global__ void __launch_bounds__(128) qkv_gemm_mma(const float* __restrict__ Xq,
                                                    const float* __restrict__ Xkv,
                                                    const float* __restrict__ Wq,
                                                    const float* __restrict__ Wk,
                                                    const float* __restrict__ Wv) {
    extern __shared__ uint32_t smg[];
    const int bz = blockIdx.z;
    const float* A = (bz == 0) ? Xq : Xkv;
    const float* W = (bz == 0) ? Wq : ((bz == 1) ? Wk : Wv);
    float* out     = (bz == 0) ? g_Q : ((bz == 1) ? g_K : g_V);
    const float scale = (bz == 0) ? 0.125f : 1.0f;

    const int m0 = blockIdx.y * 128;
    const int n0 = blockIdx.x * 128;
    const int tid = threadIdx.x;
    const int lane = tid & 31, wid = tid >> 5;
    const int wm = (wid & 1) << 6, wn = (wid >> 1) << 6;
    const int r = lane >> 2, cl = lane & 3;

    float acc[4][8][4];
    gemm_mainloop_cp32(A + (size_t)m0 * DM, W + (size_t)n0 * DM, smg, acc, tid);

    // Epilogue: scatter to [B,H,S,Dh], pre-rounded to tf32 (attn consumes raw).
#pragma unroll
    for (int mt = 0; mt < 4; mt++) {
#pragma unroll
        for (int nt = 0; nt < 8; nt++) {
            const int mr = m0 + wm + mt * 16 + r;
            const int nc = n0 + wn + nt * 8 + 2 * cl;
            const int b = mr >> 11, s = mr & 2047;
            const int h = nc >> 6, dh = nc & 63;
            float* p0 = out + (((size_t)(b * NH + h) * SEQ + s) * DH + dh);
            *(float2*)p0 = make_float2(__uint_as_float(f2tf32(acc[mt][nt][0] * scale)),
                                       __uint_as_float(f2tf32(acc[mt][nt][1] * scale)));
            float* p1 = out + (((size_t)(b * NH + h) * SEQ + (s + 8)) * DH + dh);
            *(float2*)p1 = make_float2(__uint_as_float(f2tf32(acc[mt][nt][2] * scale)),
                                       __uint_as_float(f2tf32(acc[mt][nt][3] * scale)));
        }
    }
}

__global__ void __launch_bounds__(128) proj_gemm_mma(const float* __restrict__ Wo,
                                                     float* __restrict__ C) {
    extern __shared__ uint32_t smg[];
    const int m0 = blockIdx.y * 128;
    const int n0 = blockIdx.x * 128;
    const int tid = threadIdx.x;
    const int lane = tid & 31, wid = tid >> 5;
    const int wm = (wid & 1) << 6, wn = (wid >> 1) << 6;
    const int r = lane >> 2, cl = lane & 3;

    float acc[4][8][4];
    gemm_mainloop_cp32(g_O + (size_t)m0 * DM, Wo + (size_t)n0 * DM, smg, acc, tid);

#pragma unroll
    for (int mt = 0; mt < 4; mt++) {
#pragma unroll
        for (int nt = 0; nt < 8; nt++) {
            const int mr = m0 + wm + mt * 16 + r;
            const int nc = n0 + wn + nt * 8 + 2 * cl;
            *(float2*)&C[(size_t)mr * DM + nc] = make_float2(acc[mt][nt][0], acc[mt][nt][1]);
            *(float2*)&C[(size_t)(mr + 8) * DM + nc] = make_float2(acc[mt][nt][2], acc[mt][nt][3]);
        }
    }
}

// ============================================================================
// Flash attention (R9, unchanged): tf32 mma + ldmatrix; Q/K/V pre-rounded.
// BQ=128, BK=64, Dh=64, 256 threads (8 warps x 16 q-rows each).
// ============================================================================
#define AST 68
#define OFF_Q 0
#define OFF_K (128 * AST)
#define OFF_V (192 * AST)
#define OFF_P (256 * AST)
#define ATTN_SMEM_BYTES (384 * AST * 4)

__global__ void __launch_bounds__(256) attn_mma() {
    extern __shared__ uint32_t sm4[];
    uint32_t* Qs = sm4 + OFF_Q;
    uint32_t* Ks = sm4 + OFF_K;
    uint32_t* Vs = sm4 + OFF_V;
    uint32_t* Ps = sm4 + OFF_P;

    const int tid = threadIdx.x;
    const int wid = tid >> 5, lane = tid & 31;
    const int r = lane >> 2, cl = lane & 3;
    const int mat = lane >> 3, lrow = lane & 7;
    const int qt = (int)(gridDim.x - 1) - (int)blockIdx.x;   // heavy first
    const int bh = blockIdx.y;
    const int q0 = qt * 128;
    const int wq = wid * 16;
    const size_t base = (size_t)bh * SEQ * DH;

    const uint32_t Qs_b = smem_u32(Qs), Ks_b = smem_u32(Ks);
    const uint32_t Vs_b = smem_u32(Vs), Ps_b = smem_u32(Ps);
    const int a_off = ((mat & 1) << 3) + lrow;
    const int a_col = (mat >> 1) << 2;
    const int b_off = ((mat >> 1) << 3) + lrow;
    const int b_col = (mat & 1) << 2;

    // Load Q tile (128 x 64), already tf32-rounded -> raw copy
    const uint32_t* gQ = (const uint32_t*)g_Q;
#pragma unroll
    for (int it = 0; it < 8; it++) {
        const int id = it * 256 + tid;
        const int row = id >> 4, f4 = (id & 15) << 2;
        uint4 v = *(const uint4*)&gQ[base + (size_t)(q0 + row) * DH + f4];
        *(uint4*)&Qs[row * AST + f4] = v;
    }

    float o[8][4];
#pragma unroll
    for (int nf = 0; nf < 8; nf++)
#pragma unroll
        for (int e = 0; e < 4; e++) o[nf][e] = 0.0f;
    float m0v = -1e30f, m1v = -1e30f, l0v = 0.0f, l1v = 0.0f;

    const int vc = tid & 63;
    const int vdg = (tid >> 6) << 4;
    const uint32_t* gK = (const uint32_t*)g_K;
    const uint32_t* gV = (const uint32_t*)g_V;

    const int ntiles = 2 * qt + 2;
    for (int t = 0; t < ntiles; t++) {
        const int k0g = t * 64;
        __syncthreads();
#pragma unroll
        for (int it = 0; it < 4; it++) {
            const int id = it * 256 + tid;
            const int c = id >> 4, f4 = (id & 15) << 2;
            uint4 v = *(const uint4*)&gK[base + (size_t)(k0g + c) * DH + f4];
            *(uint4*)&Ks[c * AST + f4] = v;
        }
#pragma unroll
        for (int i = 0; i < 4; i++) {
            uint4 v = *(const uint4*)&gV[base + (size_t)(k0g + vc) * DH + vdg + i * 4];
            Vs[(vdg + i * 4 + 0) * AST + vc] = v.x;
            Vs[(vdg + i * 4 + 1) * AST + vc] = v.y;
            Vs[(vdg + i * 4 + 2) * AST + vc] = v.z;
            Vs[(vdg + i * 4 + 3) * AST + vc] = v.w;
        }
        __syncthreads();

        // Scores: S[16 x 64] per warp
        float sfr[8][4];
#pragma unroll
        for (int nf = 0; nf < 8; nf++)
#pragma unroll
            for (int e = 0; e < 4; e++) sfr[nf][e] = 0.0f;
#pragma unroll
        for (int k = 0; k < 8; k++) {
            const int k0 = k * 8;
            uint32_t af[4], bf[4][4];
            LDSM_X4(af, Qs_b + (uint32_t)(((wq + a_off) * AST + k0 + a_col) * 4));
#pragma unroll
            for (int p = 0; p < 4; p++)
                LDSM_X4(bf[p], Ks_b + (uint32_t)(((p * 16 + b_off) * AST + k0 + b_col) * 4));
#pragma unroll
            for (int nf = 0; nf < 8; nf++)
                MMA_TF32(sfr[nf], af, bf[nf >> 1][(nf & 1) << 1], bf[nf >> 1][((nf & 1) << 1) + 1]);
        }

        // Causal mask (only diagonal-overlap tiles)
        if (t >= 2 * qt) {
            const int row0 = q0 + wq + r, row1 = row0 + 8;
#pragma unroll
            for (int nf = 0; nf < 8; nf++) {
                const int c0 = k0g + nf * 8 + 2 * cl;
                if (c0 > row0) sfr[nf][0] = -1e30f;
                if (c0 + 1 > row0) sfr[nf][1] = -1e30f;
                if (c0 > row1) sfr[nf][2] = -1e30f;
                if (c0 + 1 > row1) sfr[nf][3] = -1e30f;
            }
        }

        // Online softmax
        float mx0 = -1e30f, mx1 = -1e30f;
#pragma unroll
        for (int nf = 0; nf < 8; nf++) {
            mx0 = fmaxf(mx0, fmaxf(sfr[nf][0], sfr[nf][1]));
            mx1 = fmaxf(mx1, fmaxf(sfr[nf][2], sfr[nf][3]));
        }
        mx0 = fmaxf(mx0, __shfl_xor_sync(0xffffffffu, mx0, 1));
        mx0 = fmaxf(mx0, __shfl_xor_sync(0xffffffffu, mx0, 2));
        mx1 = fmaxf(mx1, __shfl_xor_sync(0xffffffffu, mx1, 1));
        mx1 = fmaxf(mx1, __shfl_xor_sync(0xffffffffu, mx1, 2));
        const float mn0 = fmaxf(m0v, mx0), mn1 = fmaxf(m1v, mx1);
        const float a0 = __expf(m0v - mn0), a1 = __expf(m1v - mn1);
        float rs0 = 0.0f, rs1 = 0.0f;
        uint32_t* pb0 = Ps + (wq + r) * AST + 2 * cl;
        uint32_t* pb1 = pb0 + 8 * AST;
#pragma unroll
        for (int nf = 0; nf < 8; nf++) {
            const float p0 = __expf(sfr[nf][0] - mn0);
            const float p1 = __expf(sfr[nf][1] - mn0);
            const float p2 = __expf(sfr[nf][2] - mn1);
            const float p3 = __expf(sfr[nf][3] - mn1);
            rs0 += p0 + p1;
            rs1 += p2 + p3;
            pb0[nf * 8 + 0] = f2tf32(p0);
            pb0[nf * 8 + 1] = f2tf32(p1);
            pb1[nf * 8 + 0] = f2tf32(p2);
            pb1[nf * 8 + 1] = f2tf32(p3);
        }
        rs0 += __shfl_xor_sync(0xffffffffu, rs0, 1);
        rs0 += __shfl_xor_sync(0xffffffffu, rs0, 2);
        rs1 += __shfl_xor_sync(0xffffffffu, rs1, 1);
        rs1 += __shfl_xor_sync(0xffffffffu, rs1, 2);
        l0v = l0v * a0 + rs0;
        l1v = l1v * a1 + rs1;
        m0v = mn0;
        m1v = mn1;
#pragma unroll
        for (int nf = 0; nf < 8; nf++) {
            o[nf][0] *= a0;
            o[nf][1] *= a0;
            o[nf][2] *= a1;
            o[nf][3] *= a1;
        }
        __syncwarp();

        // O += P(16x64) . V(64x64)
#pragma unroll
        for (int k = 0; k < 8; k++) {
            const int k0 = k * 8;
            uint32_t af[4], bf[4][4];
            LDSM_X4(af, Ps_b + (uint32_t)(((wq + a_off) * AST + k0 + a_col) * 4));
#pragma unroll
            for (int p = 0; p < 4; p++)
                LDSM_X4(bf[p], Vs_b + (uint32_t)(((p * 16 + b_off) * AST + k0 + b_col) * 4));
#pragma unroll
            for (int nf = 0; nf < 8; nf++)
                MMA_TF32(o[nf], af, bf[nf >> 1][(nf & 1) << 1], bf[nf >> 1][((nf & 1) << 1) + 1]);
        }
    }

    // Epilogue
    const float i0 = 1.0f / l0v, i1 = 1.0f / l1v;
    const int b = bh >> 4, h = bh & 15;
    const int row0 = q0 + wq + r, row1 = row0 + 8;
#pragma unroll
    for (int nf = 0; nf < 8; nf++) {
        const int col = h * DH + nf * 8 + 2 * cl;
        *(float2*)&g_O[(size_t)(b * SEQ + row0) * DM + col] =
            make_float2(o[nf][0] * i0, o[nf][1] * i0);
        *(float2*)&g_O[(size_t)(b * SEQ + row1) * DM + col] =
            make_float2(o[nf][2] * i1, o[nf][3] * i1);
    }
}

// ============================================================================
// Launch
// ============================================================================
extern "C" void kernel_launch(void* const* d_in, const int* in_sizes, int n_in,
                              void* d_out, int out_size) {
    const float* q  = (const float*)d_in[0];
    const float* kv = (const float*)d_in[1];
    const float* Wq = (const float*)d_in[2];
    const float* Wk = (const float*)d_in[3];
    const float* Wv = (const float*)d_in[4];
    const float* Wo = (const float*)d_in[5];
    float* out = (float*)d_out;

    cudaFuncSetAttribute(qkv_gemm_mma, cudaFuncAttributeMaxDynamicSharedMemorySize,
                         GEMM_SMEM_BYTES);
    cudaFuncSetAttribute(proj_gemm_mma, cudaFuncAttributeMaxDynamicSharedMemorySize,
                         GEMM_SMEM_BYTES);
    cudaFuncSetAttribute(attn_mma, cudaFuncAttributeMaxDynamicSharedMemorySize,
                         ATTN_SMEM_BYTES);

    qkv_gemm_mma<<<dim3(DM / 128, (BATCH * SEQ) / 128, 3), 128, GEMM_SMEM_BYTES>>>(q, kv, Wq, Wk, Wv);
    attn_mma<<<dim3(SEQ / 128, BATCH * NH), 256, ATTN_SMEM_BYTES>>>();
    proj_gemm_mma<<<dim3(DM / 128, (BATCH * SEQ) / 128), 128, GEMM_SMEM_BYTES>>>(Wo, out);
}

// round 12
// speedup vs baseline: 2.2086x; 1.3133x over previous
#include <cuda_runtime.h>
#include <cuda_fp16.h>
#include <cstdint>

#define DM   1024
#define SEQ  2048
#define BATCH 4
#define NH   16
#define DH   64

// Scratch (allocation-free). Q/K/V fp16 (same 10-bit mantissa as tf32).
__device__ __half g_Qh[BATCH * NH * SEQ * DH];   // [B,H,S,Dh], pre-scaled by Dh^-0.5
__device__ __half g_Kh[BATCH * NH * SEQ * DH];
__device__ __half g_Vh[BATCH * NH * SEQ * DH];
__device__ float  g_O[BATCH * SEQ * DM];         // [B,S,D] fp32

// ============================================================================
// Helpers
// ============================================================================
__device__ __forceinline__ uint32_t f2tf32(float x) {
    uint32_t u;
    asm("cvt.rna.tf32.f32 %0, %1;" : "=r"(u) : "f"(x));
    return u;
}
__device__ __forceinline__ uint32_t smem_u32(const void* p) {
    uint32_t a;
    asm("{ .reg .u64 t; cvta.to.shared.u64 t, %1; cvt.u32.u64 %0, t; }" : "=r"(a) : "l"(p));
    return a;
}

#define MMA_TF32(d, a, b0v, b1v)                                               \
    asm volatile("mma.sync.aligned.m16n8k8.row.col.f32.tf32.tf32.f32 "         \
                 "{%0,%1,%2,%3}, {%4,%5,%6,%7}, {%8,%9}, {%0,%1,%2,%3};"       \
                 : "+f"((d)[0]), "+f"((d)[1]), "+f"((d)[2]), "+f"((d)[3])      \
                 : "r"((a)[0]), "r"((a)[1]), "r"((a)[2]), "r"((a)[3]),         \
                   "r"(b0v), "r"(b1v))

#define MMA_F16(d, a, b0v, b1v)                                                \
    asm volatile("mma.sync.aligned.m16n8k16.row.col.f32.f16.f16.f32 "          \
                 "{%0,%1,%2,%3}, {%4,%5,%6,%7}, {%8,%9}, {%0,%1,%2,%3};"       \
                 : "+f"((d)[0]), "+f"((d)[1]), "+f"((d)[2]), "+f"((d)[3])      \
                 : "r"((a)[0]), "r"((a)[1]), "r"((a)[2]), "r"((a)[3]),         \
                   "r"(b0v), "r"(b1v))

#define LDSM_X4(d, addr)                                                       \
    asm volatile("ldmatrix.sync.aligned.m8n8.x4.shared.b16 {%0,%1,%2,%3}, [%4];" \
                 : "=r"((d)[0]), "=r"((d)[1]), "=r"((d)[2]), "=r"((d)[3])      \
                 : "r"(addr))

#define CP_ASYNC16(saddr, gptr)                                                \
    asm volatile("cp.async.cg.shared.global [%0], [%1], 16;"                   \
                 :: "r"(saddr), "l"(gptr))
#define CP_COMMIT() asm volatile("cp.async.commit_group;" ::: "memory")
#define CP_WAIT1()  asm volatile("cp.async.wait_group 1;" ::: "memory")

// ============================================================================
// GEMM (R10-validated, unchanged mainloop): CTA 128x128, 128 thr / 4 warps,
// warp tile 64x64, K-chunk 32, cp.async 3-stage, XOR-chunk swizzle.
// ============================================================================
#define KCH 32
#define HALF_STAGE (128 * KCH * 4)           // 16 KB (one matrix tile)
#define STAGE_BYTES (2 * HALF_STAGE)         // 32 KB (A + W)
#define GEMM_SMEM_BYTES (3 * STAGE_BYTES)    // 96 KB -> 2 CTAs/SM

__device__ __forceinline__ void gemm_issue_stage(const float* __restrict__ Ablk,
                                                 const float* __restrict__ Wblk,
                                                 uint32_t dst, int kbase,
                                                 int lr8, int lch) {
#pragma unroll
    for (int it = 0; it < 8; it++) {
        const int row = it * 16 + lr8;
        const uint32_t off = (uint32_t)(row * 128 + ((lch ^ (row & 7)) << 4));
        CP_ASYNC16(dst + off, Ablk + (size_t)row * DM + kbase + lch * 4);
        CP_ASYNC16(dst + HALF_STAGE + off, Wblk + (size_t)row * DM + kbase + lch * 4);
    }
}

__device__ __forceinline__ void gemm_mainloop_cp32(const float* __restrict__ Ablk,
                                                   const float* __restrict__ Wblk,
                                                   uint32_t* smg,
                                                   float (*acc)[8][4],
                                                   int tid) {
    const int lane = tid & 31;
    const int wid = tid >> 5;
    const int wm = (wid & 1) << 6;
    const int wn = (wid >> 1) << 6;
    const int mat = lane >> 3, lrow = lane & 7;
    const int a_row = wm + ((mat & 1) << 3) + lrow;   // + mt*16
    const int sel_a = mat >> 1;                       // chunk select 0/1
    const int b_row = wn + ((mat >> 1) << 3) + lrow;  // + p*16
    const int sel_b = mat & 1;
    const uint32_t smb = smem_u32(smg);

    const int lr8 = tid >> 3;     // 0..15
    const int lch = tid & 7;      // 16B chunk 0..7

#pragma unroll
    for (int mt = 0; mt < 4; mt++)
#pragma unroll
        for (int nt = 0; nt < 8; nt++)
#pragma unroll
            for (int e = 0; e < 4; e++) acc[mt][nt][e] = 0.0f;

    // prologue: stages 0,1
#pragma unroll
    for (int s = 0; s < 2; s++) {
        gemm_issue_stage(Ablk, Wblk, smb + (uint32_t)s * STAGE_BYTES, s * KCH, lr8, lch);
        CP_COMMIT();
    }

#pragma unroll 1
    for (int c = 0; c < 32; c++) {
        CP_WAIT1();                 // stage c resident (leaves c+1 pending)
        __syncthreads();            // all warps done computing chunk c-1
        if (c + 2 < 32)
            gemm_issue_stage(Ablk, Wblk, smb + (uint32_t)((c + 2) % 3) * STAGE_BYTES,
                             (c + 2) * KCH, lr8, lch);
        CP_COMMIT();

        const uint32_t asb = smb + (uint32_t)(c % 3) * STAGE_BYTES;
        const uint32_t wsb = asb + HALF_STAGE;
#pragma unroll
        for (int kc = 0; kc < 8; kc += 2) {   // k0 = kc*4 in {0,8,16,24}
            uint32_t af[4][4], bf[4][4];
#pragma unroll
            for (int mt = 0; mt < 4; mt++)
                LDSM_X4(af[mt], asb + (uint32_t)((a_row + mt * 16) * 128 +
                                                 (((kc + sel_a) ^ lrow) << 4)));
#pragma unroll
            for (int p = 0; p < 4; p++)
                LDSM_X4(bf[p], wsb + (uint32_t)((b_row + p * 16) * 128 +
                                                (((kc + sel_b) ^ lrow) << 4)));
#pragma unroll
            for (int mt = 0; mt < 4; mt++)
#pragma unroll
                for (int e = 0; e < 4; e++)
                    af[mt][e] = f2tf32(__uint_as_float(af[mt][e]));
#pragma unroll
            for (int p = 0; p < 4; p++)
#pragma unroll
                for (int e = 0; e < 4; e++)
                    bf[p][e] = f2tf32(__uint_as_float(bf[p][e]));
#pragma unroll
            for (int nt = 0; nt < 8; nt++) {
                const uint32_t b0 = bf[nt >> 1][(nt & 1) << 1];
                const uint32_t b1 = bf[nt >> 1][((nt & 1) << 1) + 1];
#pragma unroll
                for (int mt = 0; mt < 4; mt++)
                    MMA_TF32(acc[mt][nt], af[mt], b0, b1);
            }
        }
    }
}

__global__ void __launch_bounds__(128) qkv_gemm_mma(const float* __restrict__ Xq,
                                                    const float* __restrict__ Xkv,
                                                    const float* __restrict__ Wq,
                                                    const float* __restrict__ Wk,
                                                    const float* __restrict__ Wv) {
    extern __shared__ uint32_t smg[];
    const int bz = blockIdx.z;
    const float* A = (bz == 0) ? Xq : Xkv;
    const float* W = (bz == 0) ? Wq : ((bz == 1) ? Wk : Wv);
    __half* out    = (bz == 0) ? g_Qh : ((bz == 1) ? g_Kh : g_Vh);
    const float scale = (bz == 0) ? 0.125f : 1.0f;

    const int m0 = blockIdx.y * 128;
    const int n0 = blockIdx.x * 128;
    const int tid = threadIdx.x;
    const int lane = tid & 31, wid = tid >> 5;
    const int wm = (wid & 1) << 6, wn = (wid >> 1) << 6;
    const int r = lane >> 2, cl = lane & 3;

    float acc[4][8][4];
    gemm_mainloop_cp32(A + (size_t)m0 * DM, W + (size_t)n0 * DM, smg, acc, tid);

    // Epilogue: scatter to [B,H,S,Dh] as fp16.
#pragma unroll
    for (int mt = 0; mt < 4; mt++) {
#pragma unroll
        for (int nt = 0; nt < 8; nt++) {
            const int mr = m0 + wm + mt * 16 + r;
            const int nc = n0 + wn + nt * 8 + 2 * cl;
            const int b = mr >> 11, s = mr & 2047;
            const int h = nc >> 6, dh = nc & 63;
            __half2 h0 = __floats2half2_rn(acc[mt][nt][0] * scale, acc[mt][nt][1] * scale);
            __half2 h1 = __floats2half2_rn(acc[mt][nt][2] * scale, acc[mt][nt][3] * scale);
            *(__half2*)(out + (((size_t)(b * NH + h) * SEQ + s) * DH + dh)) = h0;
            *(__half2*)(out + (((size_t)(b * NH + h) * SEQ + (s + 8)) * DH + dh)) = h1;
        }
    }
}

__global__ void __launch_bounds__(128) proj_gemm_mma(const float* __restrict__ Wo,
                                                     float* __restrict__ C) {
    extern __shared__ uint32_t smg[];
    const int m0 = blockIdx.y * 128;
    const int n0 = blockIdx.x * 128;
    const int tid = threadIdx.x;
    const int lane = tid & 31, wid = tid >> 5;
    const int wm = (wid & 1) << 6, wn = (wid >> 1) << 6;
    const int r = lane >> 2, cl = lane & 3;

    float acc[4][8][4];
    gemm_mainloop_cp32(g_O + (size_t)m0 * DM, Wo + (size_t)n0 * DM, smg, acc, tid);

#pragma unroll
    for (int mt = 0; mt < 4; mt++) {
#pragma unroll
        for (int nt = 0; nt < 8; nt++) {
            const int mr = m0 + wm + mt * 16 + r;
            const int nc = n0 + wn + nt * 8 + 2 * cl;
            *(float2*)&C[(size_t)mr * DM + nc] = make_float2(acc[mt][nt][0], acc[mt][nt][1]);
            *(float2*)&C[(size_t)(mr + 8) * DM + nc] = make_float2(acc[mt][nt][2], acc[mt][nt][3]);
        }
    }
}

// ============================================================================
// Flash attention, fp16 mma.m16n8k16 + ldmatrix.
// BQ=128, BK=64, Dh=64, 256 threads (8 warps x 16 q-rows each).
// smem (exact-128B rows, XOR-chunk swizzle row&7):
//   Q [128][64h] 16KB | K [64][64h] 8KB | Vt [64][64h] 8KB | P [128][64h] 16KB
// ============================================================================
#define QW 0
#define KW 4096
#define VW 6144
#define PW 8192
#define ATTN_SMEM_BYTES (12288 * 4)

__global__ void __launch_bounds__(256) attn_mma() {
    extern __shared__ uint32_t sm4[];
    __half* smh = (__half*)sm4;

    const int tid = threadIdx.x;
    const int wid = tid >> 5, lane = tid & 31;
    const int r = lane >> 2, cl = lane & 3;
    const int mat = lane >> 3, lrow = lane & 7;
    const int qt = (int)(gridDim.x - 1) - (int)blockIdx.x;   // heavy first
    const int bh = blockIdx.y;
    const int q0 = qt * 128;
    const int wq = wid * 16;
    const size_t base = (size_t)bh * SEQ * DH;

    const uint32_t smb = smem_u32(sm4);
    const uint32_t Qs_b = smb + QW * 4;
    const uint32_t Ks_b = smb + KW * 4;
    const uint32_t Vs_b = smb + VW * 4;
    const uint32_t Ps_b = smb + PW * 4;

    // fragment addressing constants (fp16 m16n8k16)
    const int a_off = ((mat & 1) << 3) + lrow;   // row within 16-row a-tile
    const int sel_a = mat >> 1;                  // 16B k-chunk within k16
    const int b_off = ((mat >> 1) << 3) + lrow;  // row within 16-row b-pair
    const int sel_b = mat & 1;

    // Load Q tile (128 x 64 fp16) with XOR swizzle
#pragma unroll
    for (int it = 0; it < 4; it++) {
        const int id = it * 256 + tid;
        const int row = id >> 3, ch = id & 7;
        uint4 v = *(const uint4*)(g_Qh + base + (size_t)(q0 + row) * DH + ch * 8);
        *(uint4*)((char*)sm4 + row * 128 + ((ch ^ (row & 7)) << 4)) = v;
    }

    float o[8][4];
#pragma unroll
    for (int nf = 0; nf < 8; nf++)
#pragma unroll
        for (int e = 0; e < 4; e++) o[nf][e] = 0.0f;
    float m0v = -1e30f, m1v = -1e30f, l0v = 0.0f, l1v = 0.0f;

    const int vc = tid & 63;            // V source row (k-position)
    const int vdg = (tid >> 6) << 4;    // 16 d-values per thread

    const int ntiles = 2 * qt + 2;
    for (int t = 0; t < ntiles; t++) {
        const int k0g = t * 64;
        __syncthreads();
        // K tile -> Ks[c][d] fp16, swizzled
#pragma unroll
        for (int it = 0; it < 2; it++) {
            const int id = it * 256 + tid;
            const int row = id >> 3, ch = id & 7;
            uint4 v = *(const uint4*)(g_Kh + base + (size_t)(k0g + row) * DH + ch * 8);
            *(uint4*)((char*)sm4 + KW * 4 + row * 128 + ((ch ^ (row & 7)) << 4)) = v;
        }
        // V tile transposed -> Vt[d][c] fp16, swizzled
        {
            const __half* src = g_Vh + base + (size_t)(k0g + vc) * DH + vdg;
            uint4 v0 = *(const uint4*)(src);
            uint4 v1 = *(const uint4*)(src + 8);
            const __half* h0 = (const __half*)&v0;
            const __half* h1 = (const __half*)&v1;
#pragma unroll
            for (int j = 0; j < 8; j++) {
                const int d0 = vdg + j;
                smh[VW * 2 + d0 * 64 + (((vc >> 3) ^ (d0 & 7)) << 3) + (vc & 7)] = h0[j];
                const int d1 = vdg + 8 + j;
                smh[VW * 2 + d1 * 64 + (((vc >> 3) ^ (d1 & 7)) << 3) + (vc & 7)] = h1[j];
            }
        }
        __syncthreads();

        // Scores: S[16 x 64] per warp = Q . K^T  (4 k16 chunks over Dh=64)
        float sfr[8][4];
#pragma unroll
        for (int nf = 0; nf < 8; nf++)
#pragma unroll
            for (int e = 0; e < 4; e++) sfr[nf][e] = 0.0f;
#pragma unroll
        for (int kc = 0; kc < 4; kc++) {
            uint32_t af[4], bf[4][4];
            LDSM_X4(af, Qs_b + (uint32_t)((wq + a_off) * 128 +
                                          (((kc * 2 + sel_a) ^ lrow) << 4)));
#pragma unroll
            for (int p = 0; p < 4; p++)
                LDSM_X4(bf[p], Ks_b + (uint32_t)((p * 16 + b_off) * 128 +
                                                 (((kc * 2 + sel_b) ^ lrow) << 4)));
#pragma unroll
            for (int p = 0; p < 4; p++) {
                // regs: [0]=n0-7/k0-7 [1]=n0-7/k8-15 [2]=n8-15/k0-7 [3]=n8-15/k8-15
                MMA_F16(sfr[2 * p],     af, bf[p][0], bf[p][1]);
                MMA_F16(sfr[2 * p + 1], af, bf[p][2], bf[p][3]);
            }
        }

        // Causal mask (only diagonal-overlap tiles)
        if (t >= 2 * qt) {
            const int row0 = q0 + wq + r, row1 = row0 + 8;
#pragma unroll
            for (int nf = 0; nf < 8; nf++) {
                const int c0 = k0g + nf * 8 + 2 * cl;
                if (c0 > row0) sfr[nf][0] = -1e30f;
                if (c0 + 1 > row0) sfr[nf][1] = -1e30f;
                if (c0 > row1) sfr[nf][2] = -1e30f;
                if (c0 + 1 > row1) sfr[nf][3] = -1e30f;
            }
        }

        // Online softmax
        float mx0 = -1e30f, mx1 = -1e30f;
#pragma unroll
        for (int nf = 0; nf < 8; nf++) {
            mx0 = fmaxf(mx0, fmaxf(sfr[nf][0], sfr[nf][1]));
            mx1 = fmaxf(mx1, fmaxf(sfr[nf][2], sfr[nf][3]));
        }
        mx0 = fmaxf(mx0, __shfl_xor_sync(0xffffffffu, mx0, 1));
        mx0 = fmaxf(mx0, __shfl_xor_sync(0xffffffffu, mx0, 2));
        mx1 = fmaxf(mx1, __shfl_xor_sync(0xffffffffu, mx1, 1));
        mx1 = fmaxf(mx1, __shfl_xor_sync(0xffffffffu, mx1, 2));
        const float mn0 = fmaxf(m0v, mx0), mn1 = fmaxf(m1v, mx1);
        const float a0 = __expf(m0v - mn0), a1 = __expf(m1v - mn1);
        float rs0 = 0.0f, rs1 = 0.0f;
        // P rows wq+r and wq+r+8, col nf*8+2cl -> swizzled half2 store
        uint32_t* prow0 = sm4 + PW + (wq + r) * 32 + cl;
        uint32_t* prow1 = prow0 + 256;   // +8 rows * 32 words
#pragma unroll
        for (int nf = 0; nf < 8; nf++) {
            const float p0 = __expf(sfr[nf][0] - mn0);
            const float p1 = __expf(sfr[nf][1] - mn0);
            const float p2 = __expf(sfr[nf][2] - mn1);
            const float p3 = __expf(sfr[nf][3] - mn1);
            rs0 += p0 + p1;
            rs1 += p2 + p3;
            __half2 hp0 = __floats2half2_rn(p0, p1);
            __half2 hp1 = __floats2half2_rn(p2, p3);
            prow0[(nf ^ r) << 2] = *(uint32_t*)&hp0;
            prow1[(nf ^ r) << 2] = *(uint32_t*)&hp1;
        }
        rs0 += __shfl_xor_sync(0xffffffffu, rs0, 1);
        rs0 += __shfl_xor_sync(0xffffffffu, rs0, 2);
        rs1 += __shfl_xor_sync(0xffffffffu, rs1, 1);
        rs1 += __shfl_xor_sync(0xffffffffu, rs1, 2);
        l0v = l0v * a0 + rs0;
        l1v = l1v * a1 + rs1;
        m0v = mn0;
        m1v = mn1;
#pragma unroll
        for (int nf = 0; nf < 8; nf++) {
            o[nf][0] *= a0;
            o[nf][1] *= a0;
            o[nf][2] *= a1;
            o[nf][3] *= a1;
        }
        __syncwarp();   // P rows are warp-private

        // O += P(16x64) . V(64x64)   (4 k16 chunks over BK=64)
#pragma unroll
        for (int kc = 0; kc < 4; kc++) {
            uint32_t af[4], bf[4][4];
            LDSM_X4(af, Ps_b + (uint32_t)((wq + a_off) * 128 +
                                          (((kc * 2 + sel_a) ^ lrow) << 4)));
#pragma unroll
            for (int p = 0; p < 4; p++)
                LDSM_X4(bf[p], Vs_b + (uint32_t)((p * 16 + b_off) * 128 +
                                                 (((kc * 2 + sel_b) ^ lrow) << 4)));
#pragma unroll
            for (int p = 0; p < 4; p++) {
                MMA_F16(o[2 * p],     af, bf[p][0], bf[p][1]);
                MMA_F16(o[2 * p + 1], af, bf[p][2], bf[p][3]);
            }
        }
    }

    // Epilogue: normalize, write g_O [B,S,D] fp32
    const float i0 = 1.0f / l0v, i1 = 1.0f / l1v;
    const int b = bh >> 4, h = bh & 15;
    const int row0 = q0 + wq + r, row1 = row0 + 8;
#pragma unroll
    for (int nf = 0; nf < 8; nf++) {
        const int col = h * DH + nf * 8 + 2 * cl;
        *(float2*)&g_O[(size_t)(b * SEQ + row0) * DM + col] =
            make_float2(o[nf][0] * i0, o[nf][1] * i0);
        *(float2*)&g_O[(size_t)(b * SEQ + row1) * DM + col] =
            make_float2(o[nf][2] * i1, o[nf][3] * i1);
    }
}

// ============================================================================
// Launch
// ============================================================================
extern "C" void kernel_launch(void* const* d_in, const int* in_sizes, int n_in,
                              void* d_out, int out_size) {
    const float* q  = (const float*)d_in[0];
    const float* kv = (const float*)d_in[1];
    const float* Wq = (const float*)d_in[2];
    const float* Wk = (const float*)d_in[3];
    const float* Wv = (const float*)d_in[4];
    const float* Wo = (const float*)d_in[5];
    float* out = (float*)d_out;

    cudaFuncSetAttribute(qkv_gemm_mma, cudaFuncAttributeMaxDynamicSharedMemorySize,
                         GEMM_SMEM_BYTES);
    cudaFuncSetAttribute(proj_gemm_mma, cudaFuncAttributeMaxDynamicSharedMemorySize,
                         GEMM_SMEM_BYTES);
    cudaFuncSetAttribute(attn_mma, cudaFuncAttributeMaxDynamicSharedMemorySize,
                         ATTN_SMEM_BYTES);

    qkv_gemm_mma<<<dim3(DM / 128, (BATCH * SEQ) / 128, 3), 128, GEMM_SMEM_BYTES>>>(q, kv, Wq, Wk, Wv);
    attn_mma<<<dim3(SEQ / 128, BATCH * NH), 256, ATTN_SMEM_BYTES>>>();
    proj_gemm_mma<<<dim3(DM / 128, (BATCH * SEQ) / 128), 128, GEMM_SMEM_BYTES>>>(Wo, out);
}

// round 13
// speedup vs baseline: 3.1533x; 1.4277x over previous
#include <cuda_runtime.h>
#include <cuda_fp16.h>
#include <cstdint>

#define DM   1024
#define SEQ  2048
#define BATCH 4
#define NH   16
#define DH   64

// Scratch (allocation-free), all fp16 except nothing:
__device__ __align__(16) __half g_Xq_h[BATCH * SEQ * DM];    // query in fp16
__device__ __align__(16) __half g_Xkv_h[BATCH * SEQ * DM];   // key_value in fp16
__device__ __align__(16) __half g_Wh[4 * DM * DM];           // Wq,Wk,Wv,Wo fp16
__device__ __align__(16) __half g_Qh[BATCH * NH * SEQ * DH]; // [B,H,S,Dh], pre-scaled
__device__ __align__(16) __half g_Kh[BATCH * NH * SEQ * DH];
__device__ __align__(16) __half g_Vh[BATCH * NH * SEQ * DH];
__device__ __align__(16) __half g_Oh[BATCH * SEQ * DM];      // attn out [B,S,D] fp16

// ============================================================================
// Helpers
// ============================================================================
__device__ __forceinline__ uint32_t smem_u32(const void* p) {
    uint32_t a;
    asm("{ .reg .u64 t; cvta.to.shared.u64 t, %1; cvt.u32.u64 %0, t; }" : "=r"(a) : "l"(p));
    return a;
}

#define MMA_F16(d, a, b0v, b1v)                                                \
    asm volatile("mma.sync.aligned.m16n8k16.row.col.f32.f16.f16.f32 "          \
                 "{%0,%1,%2,%3}, {%4,%5,%6,%7}, {%8,%9}, {%0,%1,%2,%3};"       \
                 : "+f"((d)[0]), "+f"((d)[1]), "+f"((d)[2]), "+f"((d)[3])      \
                 : "r"((a)[0]), "r"((a)[1]), "r"((a)[2]), "r"((a)[3]),         \
                   "r"(b0v), "r"(b1v))

#define LDSM_X4(d, addr)                                                       \
    asm volatile("ldmatrix.sync.aligned.m8n8.x4.shared.b16 {%0,%1,%2,%3}, [%4];" \
                 : "=r"((d)[0]), "=r"((d)[1]), "=r"((d)[2]), "=r"((d)[3])      \
                 : "r"(addr))

#define CP_ASYNC16(saddr, gptr)                                                \
    asm volatile("cp.async.cg.shared.global [%0], [%1], 16;"                   \
                 :: "r"(saddr), "l"(gptr))
#define CP_COMMIT() asm volatile("cp.async.commit_group;" ::: "memory")
#define CP_WAIT1()  asm volatile("cp.async.wait_group 1;" ::: "memory")

// ============================================================================
// fp32 -> fp16 conversion pass (each thread: 8 floats -> 8 halves)
// which: 0=query, 1=key_value, 2..5 = Wq,Wk,Wv,Wo
// ============================================================================
__global__ void __launch_bounds__(256) f2h_kernel(const float* __restrict__ src,
                                                  int which, int n8) {
    __half* dst = (which == 0) ? g_Xq_h
                : (which == 1) ? g_Xkv_h
                : g_Wh + (size_t)(which - 2) * DM * DM;
    const int i = blockIdx.x * 256 + threadIdx.x;
    if (i < n8) {
        float4 a = ((const float4*)src)[2 * i];
        float4 b = ((const float4*)src)[2 * i + 1];
        __half2 h0 = __floats2half2_rn(a.x, a.y);
        __half2 h1 = __floats2half2_rn(a.z, a.w);
        __half2 h2 = __floats2half2_rn(b.x, b.y);
        __half2 h3 = __floats2half2_rn(b.z, b.w);
        uint4 o;
        o.x = *(uint32_t*)&h0; o.y = *(uint32_t*)&h1;
        o.z = *(uint32_t*)&h2; o.w = *(uint32_t*)&h3;
        ((uint4*)dst)[i] = o;
    }
}

// ============================================================================
// fp16 GEMM: CTA 128x128, 128 thr / 4 warps, warp tile 64x64, K-chunk 64,
// cp.async 3-stage, XOR-chunk swizzle (128B rows of 64 halves).
// C[m,n] = sum_k A[m,k] * W[n,k], fp32 accum.
// ============================================================================
#define HSTAGE (128 * 128)                   // 16 KB per matrix tile
#define STAGE_BYTES (2 * HSTAGE)             // 32 KB
#define GEMM_SMEM_BYTES (3 * STAGE_BYTES)    // 96 KB -> 2 CTAs/SM
#define NCHUNK 16                            // 1024 / 64

__device__ __forceinline__ void gemm_issue_stage_h(const __half* __restrict__ Ablk,
                                                   const __half* __restrict__ Wblk,
                                                   uint32_t dst, int kbase,
                                                   int lr8, int lch) {
#pragma unroll
    for (int it = 0; it < 8; it++) {
        const int row = it * 16 + lr8;
        const uint32_t off = (uint32_t)(row * 128 + ((lch ^ (row & 7)) << 4));
        CP_ASYNC16(dst + off, Ablk + (size_t)row * DM + kbase + lch * 8);
        CP_ASYNC16(dst + HSTAGE + off, Wblk + (size_t)row * DM + kbase + lch * 8);
    }
}

__device__ __forceinline__ void gemm_mainloop_h(const __half* __restrict__ Ablk,
                                                const __half* __restrict__ Wblk,
                                                uint32_t* smg,
                                                float (*acc)[8][4],
                                                int tid) {
    const int lane = tid & 31;
    const int wid = tid >> 5;
    const int wm = (wid & 1) << 6;
    const int wn = (wid >> 1) << 6;
    const int mat = lane >> 3, lrow = lane & 7;
    const int a_row = wm + ((mat & 1) << 3) + lrow;   // + mt*16 ; (a_row&7)==lrow
    const int sel_a = mat >> 1;                       // 16B chunk within k16
    const int b_row = wn + ((mat >> 1) << 3) + lrow;  // + p*16  ; (b_row&7)==lrow
    const int sel_b = mat & 1;
    const uint32_t smb = smem_u32(smg);

    const int lr8 = tid >> 3;     // 0..15
    const int lch = tid & 7;      // 16B chunk 0..7

#pragma unroll
    for (int mt = 0; mt < 4; mt++)
#pragma unroll
        for (int nt = 0; nt < 8; nt++)
#pragma unroll
            for (int e = 0; e < 4; e++) acc[mt][nt][e] = 0.0f;

    // prologue: stages 0,1
#pragma unroll
    for (int s = 0; s < 2; s++) {
        gemm_issue_stage_h(Ablk, Wblk, smb + (uint32_t)s * STAGE_BYTES, s * 64, lr8, lch);
        CP_COMMIT();
    }

#pragma unroll 1
    for (int c = 0; c < NCHUNK; c++) {
        CP_WAIT1();                 // stage c resident (leaves c+1 pending)
        __syncthreads();            // all warps done computing chunk c-1
        if (c + 2 < NCHUNK)
            gemm_issue_stage_h(Ablk, Wblk, smb + (uint32_t)((c + 2) % 3) * STAGE_BYTES,
                               (c + 2) * 64, lr8, lch);
        CP_COMMIT();

        const uint32_t asb = smb + (uint32_t)(c % 3) * STAGE_BYTES;
        const uint32_t wsb = asb + HSTAGE;
#pragma unroll
        for (int ks = 0; ks < 4; ks++) {   // 4 k16 steps per 64-chunk
            uint32_t af[4][4], bf[4][4];
#pragma unroll
            for (int mt = 0; mt < 4; mt++)
                LDSM_X4(af[mt], asb + (uint32_t)((a_row + mt * 16) * 128 +
                                                 (((ks * 2 + sel_a) ^ lrow) << 4)));
#pragma unroll
            for (int p = 0; p < 4; p++)
                LDSM_X4(bf[p], wsb + (uint32_t)((b_row + p * 16) * 128 +
                                                (((ks * 2 + sel_b) ^ lrow) << 4)));
#pragma unroll
            for (int p = 0; p < 4; p++) {
#pragma unroll
                for (int mt = 0; mt < 4; mt++) {
                    MMA_F16(acc[mt][2 * p],     af[mt], bf[p][0], bf[p][1]);
                    MMA_F16(acc[mt][2 * p + 1], af[mt], bf[p][2], bf[p][3]);
                }
            }
        }
    }
}

__global__ void __launch_bounds__(128) qkv_gemm_h(int unused) {
    extern __shared__ uint32_t smg[];
    const int bz = blockIdx.z;
    const __half* A = (bz == 0) ? g_Xq_h : g_Xkv_h;
    const __half* W = g_Wh + (size_t)bz * DM * DM;
    __half* out    = (bz == 0) ? g_Qh : ((bz == 1) ? g_Kh : g_Vh);
    const float scale = (bz == 0) ? 0.125f : 1.0f;

    const int m0 = blockIdx.y * 128;
    const int n0 = blockIdx.x * 128;
    const int tid = threadIdx.x;
    const int lane = tid & 31, wid = tid >> 5;
    const int wm = (wid & 1) << 6, wn = (wid >> 1) << 6;
    const int r = lane >> 2, cl = lane & 3;

    float acc[4][8][4];
    gemm_mainloop_h(A + (size_t)m0 * DM, W + (size_t)n0 * DM, smg, acc, tid);

    // Epilogue: scatter to [B,H,S,Dh] fp16 (Q pre-scaled)
#pragma unroll
    for (int mt = 0; mt < 4; mt++) {
#pragma unroll
        for (int nt = 0; nt < 8; nt++) {
            const int mr = m0 + wm + mt * 16 + r;
            const int nc = n0 + wn + nt * 8 + 2 * cl;
            const int b = mr >> 11, s = mr & 2047;
            const int h = nc >> 6, dh = nc & 63;
            __half2 h0 = __floats2half2_rn(acc[mt][nt][0] * scale, acc[mt][nt][1] * scale);
            __half2 h1 = __floats2half2_rn(acc[mt][nt][2] * scale, acc[mt][nt][3] * scale);
            *(__half2*)(out + (((size_t)(b * NH + h) * SEQ + s) * DH + dh)) = h0;
            *(__half2*)(out + (((size_t)(b * NH + h) * SEQ + (s + 8)) * DH + dh)) = h1;
        }
    }
}

__global__ void __launch_bounds__(128) proj_gemm_h(float* __restrict__ C) {
    extern __shared__ uint32_t smg[];
    const int m0 = blockIdx.y * 128;
    const int n0 = blockIdx.x * 128;
    const int tid = threadIdx.x;
    const int lane = tid & 31, wid = tid >> 5;
    const int wm = (wid & 1) << 6, wn = (wid >> 1) << 6;
    const int r = lane >> 2, cl = lane & 3;

    float acc[4][8][4];
    gemm_mainloop_h(g_Oh + (size_t)m0 * DM, g_Wh + (size_t)3 * DM * DM + (size_t)n0 * DM,
                    smg, acc, tid);

#pragma unroll
    for (int mt = 0; mt < 4; mt++) {
#pragma unroll
        for (int nt = 0; nt < 8; nt++) {
            const int mr = m0 + wm + mt * 16 + r;
            const int nc = n0 + wn + nt * 8 + 2 * cl;
            *(float2*)&C[(size_t)mr * DM + nc] = make_float2(acc[mt][nt][0], acc[mt][nt][1]);
            *(float2*)&C[(size_t)(mr + 8) * DM + nc] = make_float2(acc[mt][nt][2], acc[mt][nt][3]);
        }
    }
}

// ============================================================================
// Flash attention, fp16 mma.m16n8k16 + ldmatrix (R12-validated).
// BQ=128, BK=64, Dh=64, 256 threads (8 warps x 16 q-rows each).
// smem: Q 16KB | K 8KB | Vt 8KB | P 16KB (128B rows, XOR-chunk swizzle)
// ============================================================================
#define QW 0
#define KW 4096
#define VW 6144
#define PW 8192
#define ATTN_SMEM_BYTES (12288 * 4)

__global__ void __launch_bounds__(256) attn_mma() {
    extern __shared__ uint32_t sm4[];
    __half* smh = (__half*)sm4;

    const int tid = threadIdx.x;
    const int wid = tid >> 5, lane = tid & 31;
    const int r = lane >> 2, cl = lane & 3;
    const int mat = lane >> 3, lrow = lane & 7;
    const int qt = (int)(gridDim.x - 1) - (int)blockIdx.x;   // heavy first
    const int bh = blockIdx.y;
    const int q0 = qt * 128;
    const int wq = wid * 16;
    const size_t base = (size_t)bh * SEQ * DH;

    const uint32_t smb = smem_u32(sm4);
    const uint32_t Qs_b = smb + QW * 4;
    const uint32_t Ks_b = smb + KW * 4;
    const uint32_t Vs_b = smb + VW * 4;
    const uint32_t Ps_b = smb + PW * 4;

    const int a_off = ((mat & 1) << 3) + lrow;
    const int sel_a = mat >> 1;
    const int b_off = ((mat >> 1) << 3) + lrow;
    const int sel_b = mat & 1;

    // Load Q tile (128 x 64 fp16) with XOR swizzle
#pragma unroll
    for (int it = 0; it < 4; it++) {
        const int id = it * 256 + tid;
        const int row = id >> 3, ch = id & 7;
        uint4 v = *(const uint4*)(g_Qh + base + (size_t)(q0 + row) * DH + ch * 8);
        *(uint4*)((char*)sm4 + row * 128 + ((ch ^ (row & 7)) << 4)) = v;
    }

    float o[8][4];
#pragma unroll
    for (int nf = 0; nf < 8; nf++)
#pragma unroll
        for (int e = 0; e < 4; e++) o[nf][e] = 0.0f;
    float m0v = -1e30f, m1v = -1e30f, l0v = 0.0f, l1v = 0.0f;

    const int vc = tid & 63;
    const int vdg = (tid >> 6) << 4;

    const int ntiles = 2 * qt + 2;
    for (int t = 0; t < ntiles; t++) {
        const int k0g = t * 64;
        __syncthreads();
#pragma unroll
        for (int it = 0; it < 2; it++) {
            const int id = it * 256 + tid;
            const int row = id >> 3, ch = id & 7;
            uint4 v = *(const uint4*)(g_Kh + base + (size_t)(k0g + row) * DH + ch * 8);
            *(uint4*)((char*)sm4 + KW * 4 + row * 128 + ((ch ^ (row & 7)) << 4)) = v;
        }
        {
            const __half* src = g_Vh + base + (size_t)(k0g + vc) * DH + vdg;
            uint4 v0 = *(const uint4*)(src);
            uint4 v1 = *(const uint4*)(src + 8);
            const __half* h0 = (const __half*)&v0;
            const __half* h1 = (const __half*)&v1;
#pragma unroll
            for (int j = 0; j < 8; j++) {
                const int d0 = vdg + j;
                smh[VW * 2 + d0 * 64 + (((vc >> 3) ^ (d0 & 7)) << 3) + (vc & 7)] = h0[j];
                const int d1 = vdg + 8 + j;
                smh[VW * 2 + d1 * 64 + (((vc >> 3) ^ (d1 & 7)) << 3) + (vc & 7)] = h1[j];
            }
        }
        __syncthreads();

        // Scores
        float sfr[8][4];
#pragma unroll
        for (int nf = 0; nf < 8; nf++)
#pragma unroll
            for (int e = 0; e < 4; e++) sfr[nf][e] = 0.0f;
#pragma unroll
        for (int kc = 0; kc < 4; kc++) {
            uint32_t af[4], bf[4][4];
            LDSM_X4(af, Qs_b + (uint32_t)((wq + a_off) * 128 +
                                          (((kc * 2 + sel_a) ^ lrow) << 4)));
#pragma unroll
            for (int p = 0; p < 4; p++)
                LDSM_X4(bf[p], Ks_b + (uint32_t)((p * 16 + b_off) * 128 +
                                                 (((kc * 2 + sel_b) ^ lrow) << 4)));
#pragma unroll
            for (int p = 0; p < 4; p++) {
                MMA_F16(sfr[2 * p],     af, bf[p][0], bf[p][1]);
                MMA_F16(sfr[2 * p + 1], af, bf[p][2], bf[p][3]);
            }
        }

        // Causal mask (only diagonal-overlap tiles)
        if (t >= 2 * qt) {
            const int row0 = q0 + wq + r, row1 = row0 + 8;
#pragma unroll
            for (int nf = 0; nf < 8; nf++) {
                const int c0 = k0g + nf * 8 + 2 * cl;
                if (c0 > row0) sfr[nf][0] = -1e30f;
                if (c0 + 1 > row0) sfr[nf][1] = -1e30f;
                if (c0 > row1) sfr[nf][2] = -1e30f;
                if (c0 + 1 > row1) sfr[nf][3] = -1e30f;
            }
        }

        // Online softmax
        float mx0 = -1e30f, mx1 = -1e30f;
#pragma unroll
        for (int nf = 0; nf < 8; nf++) {
            mx0 = fmaxf(mx0, fmaxf(sfr[nf][0], sfr[nf][1]));
            mx1 = fmaxf(mx1, fmaxf(sfr[nf][2], sfr[nf][3]));
        }
        mx0 = fmaxf(mx0, __shfl_xor_sync(0xffffffffu, mx0, 1));
        mx0 = fmaxf(mx0, __shfl_xor_sync(0xffffffffu, mx0, 2));
        mx1 = fmaxf(mx1, __shfl_xor_sync(0xffffffffu, mx1, 1));
        mx1 = fmaxf(mx1, __shfl_xor_sync(0xffffffffu, mx1, 2));
        const float mn0 = fmaxf(m0v, mx0), mn1 = fmaxf(m1v, mx1);
        const float a0 = __expf(m0v - mn0), a1 = __expf(m1v - mn1);
        float rs0 = 0.0f, rs1 = 0.0f;
        uint32_t* prow0 = sm4 + PW + (wq + r) * 32 + cl;
        uint32_t* prow1 = prow0 + 256;
#pragma unroll
        for (int nf = 0; nf < 8; nf++) {
            const float p0 = __expf(sfr[nf][0] - mn0);
            const float p1 = __expf(sfr[nf][1] - mn0);
            const float p2 = __expf(sfr[nf][2] - mn1);
            const float p3 = __expf(sfr[nf][3] - mn1);
            rs0 += p0 + p1;
            rs1 += p2 + p3;
            __half2 hp0 = __floats2half2_rn(p0, p1);
            __half2 hp1 = __floats2half2_rn(p2, p3);
            prow0[(nf ^ r) << 2] = *(uint32_t*)&hp0;
            prow1[(nf ^ r) << 2] = *(uint32_t*)&hp1;
        }
        rs0 += __shfl_xor_sync(0xffffffffu, rs0, 1);
        rs0 += __shfl_xor_sync(0xffffffffu, rs0, 2);
        rs1 += __shfl_xor_sync(0xffffffffu, rs1, 1);
        rs1 += __shfl_xor_sync(0xffffffffu, rs1, 2);
        l0v = l0v * a0 + rs0;
        l1v = l1v * a1 + rs1;
        m0v = mn0;
        m1v = mn1;
#pragma unroll
        for (int nf = 0; nf < 8; nf++) {
            o[nf][0] *= a0;
            o[nf][1] *= a0;
            o[nf][2] *= a1;
            o[nf][3] *= a1;
        }
        __syncwarp();

        // O += P . V
#pragma unroll
        for (int kc = 0; kc < 4; kc++) {
            uint32_t af[4], bf[4][4];
            LDSM_X4(af, Ps_b + (uint32_t)((wq + a_off) * 128 +
                                          (((kc * 2 + sel_a) ^ lrow) << 4)));
#pragma unroll
            for (int p = 0; p < 4; p++)
                LDSM_X4(bf[p], Vs_b + (uint32_t)((p * 16 + b_off) * 128 +
                                                 (((kc * 2 + sel_b) ^ lrow) << 4)));
#pragma unroll
            for (int p = 0; p < 4; p++) {
                MMA_F16(o[2 * p],     af, bf[p][0], bf[p][1]);
                MMA_F16(o[2 * p + 1], af, bf[p][2], bf[p][3]);
            }
        }
    }

    // Epilogue: normalize, write g_Oh [B,S,D] fp16
    const float i0 = 1.0f / l0v, i1 = 1.0f / l1v;
    const int b = bh >> 4, h = bh & 15;
    const int row0 = q0 + wq + r, row1 = row0 + 8;
#pragma unroll
    for (int nf = 0; nf < 8; nf++) {
        const int col = h * DH + nf * 8 + 2 * cl;
        __half2 w0 = __floats2half2_rn(o[nf][0] * i0, o[nf][1] * i0);
        __half2 w1 = __floats2half2_rn(o[nf][2] * i1, o[nf][3] * i1);
        *(__half2*)(g_Oh + (size_t)(b * SEQ + row0) * DM + col) = w0;
        *(__half2*)(g_Oh + (size_t)(b * SEQ + row1) * DM + col) = w1;
    }
}

// ============================================================================
// Launch
// ============================================================================
extern "C" void kernel_launch(void* const* d_in, const int* in_sizes, int n_in,
                              void* d_out, int out_size) {
    const float* q  = (const float*)d_in[0];
    const float* kv = (const float*)d_in[1];
    const float* Wq = (const float*)d_in[2];
    const float* Wk = (const float*)d_in[3];
    const float* Wv = (const float*)d_in[4];
    const float* Wo = (const float*)d_in[5];
    float* out = (float*)d_out;

    cudaFuncSetAttribute(qkv_gemm_h, cudaFuncAttributeMaxDynamicSharedMemorySize,
                         GEMM_SMEM_BYTES);
    cudaFuncSetAttribute(proj_gemm_h, cudaFuncAttributeMaxDynamicSharedMemorySize,
                         GEMM_SMEM_BYTES);
    cudaFuncSetAttribute(attn_mma, cudaFuncAttributeMaxDynamicSharedMemorySize,
                         ATTN_SMEM_BYTES);

    // 1) Convert inputs + weights to fp16
    const int n8x = BATCH * SEQ * DM / 8;
    const int n8w = DM * DM / 8;
    f2h_kernel<<<(n8x + 255) / 256, 256>>>(q, 0, n8x);
    f2h_kernel<<<(n8x + 255) / 256, 256>>>(kv, 1, n8x);
    f2h_kernel<<<(n8w + 255) / 256, 256>>>(Wq, 2, n8w);
    f2h_kernel<<<(n8w + 255) / 256, 256>>>(Wk, 3, n8w);
    f2h_kernel<<<(n8w + 255) / 256, 256>>>(Wv, 4, n8w);
    f2h_kernel<<<(n8w + 255) / 256, 256>>>(Wo, 5, n8w);

    // 2) QKV projections (fp16 mma) -> [B,H,S,Dh] fp16
    qkv_gemm_h<<<dim3(DM / 128, (BATCH * SEQ) / 128, 3), 128, GEMM_SMEM_BYTES>>>(0);

    // 3) Causal flash attention (fp16 mma) -> g_Oh
    attn_mma<<<dim3(SEQ / 128, BATCH * NH), 256, ATTN_SMEM_BYTES>>>();

    // 4) Output projection (fp16 mma) -> d_out fp32
    proj_gemm_h<<<dim3(DM / 128, (BATCH * SEQ) / 128), 128, GEMM_SMEM_BYTES>>>(out);
}

// round 14
// speedup vs baseline: 3.5032x; 1.1110x over previous
#include <cuda_runtime.h>
#include <cuda_fp16.h>
#include <cstdint>

#define DM   1024
#define SEQ  2048
#define BATCH 4
#define NH   16
#define DH   64

// Scratch (allocation-free)
__device__ __align__(16) __half g_Xq_h[BATCH * SEQ * DM];    // query in fp16
__device__ __align__(16) __half g_Xkv_h[BATCH * SEQ * DM];   // key_value in fp16
__device__ __align__(16) __half g_Wh[4 * DM * DM];           // Wq,Wk,Wv,Wo fp16
__device__ __align__(16) __half g_Qh[BATCH * NH * SEQ * DH]; // [B,H,S,Dh], pre-scaled
__device__ __align__(16) __half g_Kh[BATCH * NH * SEQ * DH];
__device__ __align__(16) __half g_Vh[BATCH * NH * SEQ * DH];
__device__ __align__(16) __half g_Oh[BATCH * SEQ * DM];      // attn out [B,S,D] fp16

// ============================================================================
// Helpers
// ============================================================================
__device__ __forceinline__ uint32_t smem_u32(const void* p) {
    uint32_t a;
    asm("{ .reg .u64 t; cvta.to.shared.u64 t, %1; cvt.u32.u64 %0, t; }" : "=r"(a) : "l"(p));
    return a;
}

#define MMA_F16(d, a, b0v, b1v)                                                \
    asm volatile("mma.sync.aligned.m16n8k16.row.col.f32.f16.f16.f32 "          \
                 "{%0,%1,%2,%3}, {%4,%5,%6,%7}, {%8,%9}, {%0,%1,%2,%3};"       \
                 : "+f"((d)[0]), "+f"((d)[1]), "+f"((d)[2]), "+f"((d)[3])      \
                 : "r"((a)[0]), "r"((a)[1]), "r"((a)[2]), "r"((a)[3]),         \
                   "r"(b0v), "r"(b1v))

#define LDSM_X4(d, addr)                                                       \
    asm volatile("ldmatrix.sync.aligned.m8n8.x4.shared.b16 {%0,%1,%2,%3}, [%4];" \
                 : "=r"((d)[0]), "=r"((d)[1]), "=r"((d)[2]), "=r"((d)[3])      \
                 : "r"(addr))

#define LDSM_X4_T(d, addr)                                                     \
    asm volatile("ldmatrix.sync.aligned.m8n8.x4.trans.shared.b16 {%0,%1,%2,%3}, [%4];" \
                 : "=r"((d)[0]), "=r"((d)[1]), "=r"((d)[2]), "=r"((d)[3])      \
                 : "r"(addr))

#define CP_ASYNC16(saddr, gptr)                                                \
    asm volatile("cp.async.cg.shared.global [%0], [%1], 16;"                   \
                 :: "r"(saddr), "l"(gptr))
#define CP_COMMIT() asm volatile("cp.async.commit_group;" ::: "memory")
#define CP_WAIT0()  asm volatile("cp.async.wait_group 0;" ::: "memory")
#define CP_WAIT1()  asm volatile("cp.async.wait_group 1;" ::: "memory")

// ============================================================================
// fp32 -> fp16 conversion pass
// ============================================================================
__global__ void __launch_bounds__(256) f2h_kernel(const float* __restrict__ src,
                                                  int which, int n8) {
    __half* dst = (which == 0) ? g_Xq_h
                : (which == 1) ? g_Xkv_h
                : g_Wh + (size_t)(which - 2) * DM * DM;
    const int i = blockIdx.x * 256 + threadIdx.x;
    if (i < n8) {
        float4 a = ((const float4*)src)[2 * i];
        float4 b = ((const float4*)src)[2 * i + 1];
        __half2 h0 = __floats2half2_rn(a.x, a.y);
        __half2 h1 = __floats2half2_rn(a.z, a.w);
        __half2 h2 = __floats2half2_rn(b.x, b.y);
        __half2 h3 = __floats2half2_rn(b.z, b.w);
        uint4 o;
        o.x = *(uint32_t*)&h0; o.y = *(uint32_t*)&h1;
        o.z = *(uint32_t*)&h2; o.w = *(uint32_t*)&h3;
        ((uint4*)dst)[i] = o;
    }
}

// ============================================================================
// fp16 GEMM (R13-validated, unchanged): CTA 128x128, 4 warps, warp 64x64,
// K-chunk 64, cp.async 3-stage, XOR-chunk swizzle.
// ============================================================================
#define HSTAGE (128 * 128)
#define STAGE_BYTES (2 * HSTAGE)
#define GEMM_SMEM_BYTES (3 * STAGE_BYTES)
#define NCHUNK 16

__device__ __forceinline__ void gemm_issue_stage_h(const __half* __restrict__ Ablk,
                                                   const __half* __restrict__ Wblk,
                                                   uint32_t dst, int kbase,
                                                   int lr8, int lch) {
#pragma unroll
    for (int it = 0; it < 8; it++) {
        const int row = it * 16 + lr8;
        const uint32_t off = (uint32_t)(row * 128 + ((lch ^ (row & 7)) << 4));
        CP_ASYNC16(dst + off, Ablk + (size_t)row * DM + kbase + lch * 8);
        CP_ASYNC16(dst + HSTAGE + off, Wblk + (size_t)row * DM + kbase + lch * 8);
    }
}

__device__ __forceinline__ void gemm_mainloop_h(const __half* __restrict__ Ablk,
                                                const __half* __restrict__ Wblk,
                                                uint32_t* smg,
                                                float (*acc)[8][4],
                                                int tid) {
    const int lane = tid & 31;
    const int wid = tid >> 5;
    const int wm = (wid & 1) << 6;
    const int wn = (wid >> 1) << 6;
    const int mat = lane >> 3, lrow = lane & 7;
    const int a_row = wm + ((mat & 1) << 3) + lrow;
    const int sel_a = mat >> 1;
    const int b_row = wn + ((mat >> 1) << 3) + lrow;
    const int sel_b = mat & 1;
    const uint32_t smb = smem_u32(smg);

    const int lr8 = tid >> 3;
    const int lch = tid & 7;

#pragma unroll
    for (int mt = 0; mt < 4; mt++)
#pragma unroll
        for (int nt = 0; nt < 8; nt++)
#pragma unroll
            for (int e = 0; e < 4; e++) acc[mt][nt][e] = 0.0f;

#pragma unroll
    for (int s = 0; s < 2; s++) {
        gemm_issue_stage_h(Ablk, Wblk, smb + (uint32_t)s * STAGE_BYTES, s * 64, lr8, lch);
        CP_COMMIT();
    }

#pragma unroll 1
    for (int c = 0; c < NCHUNK; c++) {
        CP_WAIT1();
        __syncthreads();
        if (c + 2 < NCHUNK)
            gemm_issue_stage_h(Ablk, Wblk, smb + (uint32_t)((c + 2) % 3) * STAGE_BYTES,
                               (c + 2) * 64, lr8, lch);
        CP_COMMIT();

        const uint32_t asb = smb + (uint32_t)(c % 3) * STAGE_BYTES;
        const uint32_t wsb = asb + HSTAGE;
#pragma unroll
        for (int ks = 0; ks < 4; ks++) {
            uint32_t af[4][4], bf[4][4];
#pragma unroll
            for (int mt = 0; mt < 4; mt++)
                LDSM_X4(af[mt], asb + (uint32_t)((a_row + mt * 16) * 128 +
                                                 (((ks * 2 + sel_a) ^ lrow) << 4)));
#pragma unroll
            for (int p = 0; p < 4; p++)
                LDSM_X4(bf[p], wsb + (uint32_t)((b_row + p * 16) * 128 +
                                                (((ks * 2 + sel_b) ^ lrow) << 4)));
#pragma unroll
            for (int p = 0; p < 4; p++) {
#pragma unroll
                for (int mt = 0; mt < 4; mt++) {
                    MMA_F16(acc[mt][2 * p],     af[mt], bf[p][0], bf[p][1]);
                    MMA_F16(acc[mt][2 * p + 1], af[mt], bf[p][2], bf[p][3]);
                }
            }
        }
    }
}

__global__ void __launch_bounds__(128) qkv_gemm_h(int unused) {
    extern __shared__ uint32_t smg[];
    const int bz = blockIdx.z;
    const __half* A = (bz == 0) ? g_Xq_h : g_Xkv_h;
    const __half* W = g_Wh + (size_t)bz * DM * DM;
    __half* out    = (bz == 0) ? g_Qh : ((bz == 1) ? g_Kh : g_Vh);
    const float scale = (bz == 0) ? 0.125f : 1.0f;

    const int m0 = blockIdx.y * 128;
    const int n0 = blockIdx.x * 128;
    const int tid = threadIdx.x;
    const int lane = tid & 31, wid = tid >> 5;
    const int wm = (wid & 1) << 6, wn = (wid >> 1) << 6;
    const int r = lane >> 2, cl = lane & 3;

    float acc[4][8][4];
    gemm_mainloop_h(A + (size_t)m0 * DM, W + (size_t)n0 * DM, smg, acc, tid);

#pragma unroll
    for (int mt = 0; mt < 4; mt++) {
#pragma unroll
        for (int nt = 0; nt < 8; nt++) {
            const int mr = m0 + wm + mt * 16 + r;
            const int nc = n0 + wn + nt * 8 + 2 * cl;
            const int b = mr >> 11, s = mr & 2047;
            const int h = nc >> 6, dh = nc & 63;
            __half2 h0 = __floats2half2_rn(acc[mt][nt][0] * scale, acc[mt][nt][1] * scale);
            __half2 h1 = __floats2half2_rn(acc[mt][nt][2] * scale, acc[mt][nt][3] * scale);
            *(__half2*)(out + (((size_t)(b * NH + h) * SEQ + s) * DH + dh)) = h0;
            *(__half2*)(out + (((size_t)(b * NH + h) * SEQ + (s + 8)) * DH + dh)) = h1;
        }
    }
}

__global__ void __launch_bounds__(128) proj_gemm_h(float* __restrict__ C) {
    extern __shared__ uint32_t smg[];
    const int m0 = blockIdx.y * 128;
    const int n0 = blockIdx.x * 128;
    const int tid = threadIdx.x;
    const int lane = tid & 31, wid = tid >> 5;
    const int wm = (wid & 1) << 6, wn = (wid >> 1) << 6;
    const int r = lane >> 2, cl = lane & 3;

    float acc[4][8][4];
    gemm_mainloop_h(g_Oh + (size_t)m0 * DM, g_Wh + (size_t)3 * DM * DM + (size_t)n0 * DM,
                    smg, acc, tid);

#pragma unroll
    for (int mt = 0; mt < 4; mt++) {
#pragma unroll
        for (int nt = 0; nt < 8; nt++) {
            const int mr = m0 + wm + mt * 16 + r;
            const int nc = n0 + wn + nt * 8 + 2 * cl;
            *(float2*)&C[(size_t)mr * DM + nc] = make_float2(acc[mt][nt][0], acc[mt][nt][1]);
            *(float2*)&C[(size_t)(mr + 8) * DM + nc] = make_float2(acc[mt][nt][2], acc[mt][nt][3]);
        }
    }
}

// ============================================================================
// Flash attention, fp16 mma + ldmatrix; cp.async double-buffered K/V;
// V kept row-major [c][d], PV B-fragments via ldmatrix.trans.
// BQ=128, BK=64, Dh=64, 256 threads (8 warps x 16 q-rows each).
// smem bytes: Q[0,16K) P[16K,32K) K0[32K,40K) V0[40K,48K) K1[48K,56K) V1[56K,64K)
// ============================================================================
#define AQ_B 0
#define AP_B 16384
#define AKV_B 32768
#define ATTN_SMEM_BYTES 65536

__global__ void __launch_bounds__(256) attn_mma() {
    extern __shared__ uint32_t sm4[];

    const int tid = threadIdx.x;
    const int wid = tid >> 5, lane = tid & 31;
    const int r = lane >> 2, cl = lane & 3;
    const int mat = lane >> 3, lrow = lane & 7;
    const int qt = (int)(gridDim.x - 1) - (int)blockIdx.x;   // heavy first
    const int bh = blockIdx.y;
    const int q0 = qt * 128;
    const int wq = wid * 16;
    const size_t base = (size_t)bh * SEQ * DH;

    const uint32_t smb = smem_u32(sm4);
    const uint32_t Qs_b = smb + AQ_B;
    const uint32_t Ps_b = smb + AP_B;

    const int a_off = ((mat & 1) << 3) + lrow;   // a-frag row offset (a_off&7==lrow)
    const int sel_a = mat >> 1;                  // 16B k-chunk select
    const int b_off = ((mat >> 1) << 3) + lrow;  // K b-frag row offset
    const int sel_b = mat & 1;

    // cp.async loader mapping: 2 chunks per thread per 8KB tile
    const int ld_row = tid >> 3;                 // 0..31 (+32)
    const int ld_ch = tid & 7;

    // Load Q tile (128 x 64 fp16), XOR swizzle
#pragma unroll
    for (int it = 0; it < 4; it++) {
        const int id = it * 256 + tid;
        const int row = id >> 3, ch = id & 7;
        uint4 v = *(const uint4*)(g_Qh + base + (size_t)(q0 + row) * DH + ch * 8);
        *(uint4*)((char*)sm4 + row * 128 + ((ch ^ (row & 7)) << 4)) = v;
    }

    float o[8][4];
#pragma unroll
    for (int nf = 0; nf < 8; nf++)
#pragma unroll
        for (int e = 0; e < 4; e++) o[nf][e] = 0.0f;
    float m0v = -1e30f, m1v = -1e30f, l0v = 0.0f, l1v = 0.0f;

    const int ntiles = 2 * qt + 2;

    // Prologue: issue K/V tile 0 into buffer 0
    {
        const uint32_t kb = smb + AKV_B;
#pragma unroll
        for (int it = 0; it < 2; it++) {
            const int row = it * 32 + ld_row;
            const uint32_t off = (uint32_t)(row * 128 + ((ld_ch ^ (row & 7)) << 4));
            CP_ASYNC16(kb + off, g_Kh + base + (size_t)row * DH + ld_ch * 8);
            CP_ASYNC16(kb + 8192 + off, g_Vh + base + (size_t)row * DH + ld_ch * 8);
        }
        CP_COMMIT();
    }

#pragma unroll 1
    for (int t = 0; t < ntiles; t++) {
        const int k0g = t * 64;
        CP_WAIT0();
        __syncthreads();   // copies visible to all; prev compute done

        // Issue next tile into the other buffer (overlaps with this compute)
        if (t + 1 < ntiles) {
            const uint32_t kb = smb + AKV_B + (uint32_t)((t + 1) & 1) * 16384;
            const int kn = (t + 1) * 64;
#pragma unroll
            for (int it = 0; it < 2; it++) {
                const int row = it * 32 + ld_row;
                const uint32_t off = (uint32_t)(row * 128 + ((ld_ch ^ (row & 7)) << 4));
                CP_ASYNC16(kb + off, g_Kh + base + (size_t)(kn + row) * DH + ld_ch * 8);
                CP_ASYNC16(kb + 8192 + off, g_Vh + base + (size_t)(kn + row) * DH + ld_ch * 8);
            }
        }
        CP_COMMIT();

        const uint32_t Ks_b = smb + AKV_B + (uint32_t)(t & 1) * 16384;
        const uint32_t Vs_b = Ks_b + 8192;

        // Scores: S[16 x 64] per warp
        float sfr[8][4];
#pragma unroll
        for (int nf = 0; nf < 8; nf++)
#pragma unroll
            for (int e = 0; e < 4; e++) sfr[nf][e] = 0.0f;
#pragma unroll
        for (int kc = 0; kc < 4; kc++) {
            uint32_t af[4], bf[4][4];
            LDSM_X4(af, Qs_b + (uint32_t)((wq + a_off) * 128 +
                                          (((kc * 2 + sel_a) ^ lrow) << 4)));
#pragma unroll
            for (int p = 0; p < 4; p++)
                LDSM_X4(bf[p], Ks_b + (uint32_t)((p * 16 + b_off) * 128 +
                                                 (((kc * 2 + sel_b) ^ lrow) << 4)));
#pragma unroll
            for (int p = 0; p < 4; p++) {
                MMA_F16(sfr[2 * p],     af, bf[p][0], bf[p][1]);
                MMA_F16(sfr[2 * p + 1], af, bf[p][2], bf[p][3]);
            }
        }

        // Causal mask (only diagonal-overlap tiles)
        if (t >= 2 * qt) {
            const int row0 = q0 + wq + r, row1 = row0 + 8;
#pragma unroll
            for (int nf = 0; nf < 8; nf++) {
                const int c0 = k0g + nf * 8 + 2 * cl;
                if (c0 > row0) sfr[nf][0] = -1e30f;
                if (c0 + 1 > row0) sfr[nf][1] = -1e30f;
                if (c0 > row1) sfr[nf][2] = -1e30f;
                if (c0 + 1 > row1) sfr[nf][3] = -1e30f;
            }
        }

        // Online softmax
        float mx0 = -1e30f, mx1 = -1e30f;
#pragma unroll
        for (int nf = 0; nf < 8; nf++) {
            mx0 = fmaxf(mx0, fmaxf(sfr[nf][0], sfr[nf][1]));
            mx1 = fmaxf(mx1, fmaxf(sfr[nf][2], sfr[nf][3]));
        }
        mx0 = fmaxf(mx0, __shfl_xor_sync(0xffffffffu, mx0, 1));
        mx0 = fmaxf(mx0, __shfl_xor_sync(0xffffffffu, mx0, 2));
        mx1 = fmaxf(mx1, __shfl_xor_sync(0xffffffffu, mx1, 1));
        mx1 = fmaxf(mx1, __shfl_xor_sync(0xffffffffu, mx1, 2));
        const float mn0 = fmaxf(m0v, mx0), mn1 = fmaxf(m1v, mx1);
        const float a0 = __expf(m0v - mn0), a1 = __expf(m1v - mn1);
        float rs0 = 0.0f, rs1 = 0.0f;
        uint32_t* prow0 = sm4 + AP_B / 4 + (wq + r) * 32 + cl;
        uint32_t* prow1 = prow0 + 256;
#pragma unroll
        for (int nf = 0; nf < 8; nf++) {
            const float p0 = __expf(sfr[nf][0] - mn0);
            const float p1 = __expf(sfr[nf][1] - mn0);
            const float p2 = __expf(sfr[nf][2] - mn1);
            const float p3 = __expf(sfr[nf][3] - mn1);
            rs0 += p0 + p1;
            rs1 += p2 + p3;
            __half2 hp0 = __floats2half2_rn(p0, p1);
            __half2 hp1 = __floats2half2_rn(p2, p3);
            prow0[(nf ^ r) << 2] = *(uint32_t*)&hp0;
            prow1[(nf ^ r) << 2] = *(uint32_t*)&hp1;
        }
        rs0 += __shfl_xor_sync(0xffffffffu, rs0, 1);
        rs0 += __shfl_xor_sync(0xffffffffu, rs0, 2);
        rs1 += __shfl_xor_sync(0xffffffffu, rs1, 1);
        rs1 += __shfl_xor_sync(0xffffffffu, rs1, 2);
        l0v = l0v * a0 + rs0;
        l1v = l1v * a1 + rs1;
        m0v = mn0;
        m1v = mn1;
#pragma unroll
        for (int nf = 0; nf < 8; nf++) {
            o[nf][0] *= a0;
            o[nf][1] *= a0;
            o[nf][2] *= a1;
            o[nf][3] *= a1;
        }
        __syncwarp();   // P rows are warp-private

        // O += P(16x64) . V(64x64); V row-major, B-frags via ldmatrix.trans.
        // trans matrix j: j0=c0-7/d0-7 j1=c8-15/d0-7 j2=c0-7/d8-15 j3=c8-15/d8-15
        // -> regs = {n0-7/k0-7, n0-7/k8-15, n8-15/k0-7, n8-15/k8-15} (validated pairing)
#pragma unroll
        for (int kc = 0; kc < 4; kc++) {
            uint32_t af[4], bf[4][4];
            LDSM_X4(af, Ps_b + (uint32_t)((wq + a_off) * 128 +
                                          (((kc * 2 + sel_a) ^ lrow) << 4)));
            const int vrow = kc * 16 + a_off;   // c-row for this lane's matrix
#pragma unroll
            for (int p = 0; p < 4; p++)
                LDSM_X4_T(bf[p], Vs_b + (uint32_t)(vrow * 128 +
                                                   (((2 * p + sel_a) ^ lrow) << 4)));
#pragma unroll
            for (int p = 0; p < 4; p++) {
                MMA_F16(o[2 * p],     af, bf[p][0], bf[p][1]);
                MMA_F16(o[2 * p + 1], af, bf[p][2], bf[p][3]);
            }
        }
    }

    // Epilogue: normalize, write g_Oh [B,S,D] fp16
    const float i0 = 1.0f / l0v, i1 = 1.0f / l1v;
    const int b = bh >> 4, h = bh & 15;
    const int row0 = q0 + wq + r, row1 = row0 + 8;
#pragma unroll
    for (int nf = 0; nf < 8; nf++) {
        const int col = h * DH + nf * 8 + 2 * cl;
        __half2 w0 = __floats2half2_rn(o[nf][0] * i0, o[nf][1] * i0);
        __half2 w1 = __floats2half2_rn(o[nf][2] * i1, o[nf][3] * i1);
        *(__half2*)(g_Oh + (size_t)(b * SEQ + row0) * DM + col) = w0;
        *(__half2*)(g_Oh + (size_t)(b * SEQ + row1) * DM + col) = w1;
    }
}

// ============================================================================
// Launch
// ============================================================================
extern "C" void kernel_launch(void* const* d_in, const int* in_sizes, int n_in,
                              void* d_out, int out_size) {
    const float* q  = (const float*)d_in[0];
    const float* kv = (const float*)d_in[1];
    const float* Wq = (const float*)d_in[2];
    const float* Wk = (const float*)d_in[3];
    const float* Wv = (const float*)d_in[4];
    const float* Wo = (const float*)d_in[5];
    float* out = (float*)d_out;

    cudaFuncSetAttribute(qkv_gemm_h, cudaFuncAttributeMaxDynamicSharedMemorySize,
                         GEMM_SMEM_BYTES);
    cudaFuncSetAttribute(proj_gemm_h, cudaFuncAttributeMaxDynamicSharedMemorySize,
                         GEMM_SMEM_BYTES);
    cudaFuncSetAttribute(attn_mma, cudaFuncAttributeMaxDynamicSharedMemorySize,
                         ATTN_SMEM_BYTES);

    const int n8x = BATCH * SEQ * DM / 8;
    const int n8w = DM * DM / 8;
    f2h_kernel<<<(n8x + 255) / 256, 256>>>(q, 0, n8x);
    f2h_kernel<<<(n8x + 255) / 256, 256>>>(kv, 1, n8x);
    f2h_kernel<<<(n8w + 255) / 256, 256>>>(Wq, 2, n8w);
    f2h_kernel<<<(n8w + 255) / 256, 256>>>(Wk, 3, n8w);
    f2h_kernel<<<(n8w + 255) / 256, 256>>>(Wv, 4, n8w);
    f2h_kernel<<<(n8w + 255) / 256, 256>>>(Wo, 5, n8w);

    qkv_gemm_h<<<dim3(DM / 128, (BATCH * SEQ) / 128, 3), 128, GEMM_SMEM_BYTES>>>(0);
    attn_mma<<<dim3(SEQ / 128, BATCH * NH), 256, ATTN_SMEM_BYTES>>>();
    proj_gemm_h<<<dim3(DM / 128, (BATCH * SEQ) / 128), 128, GEMM_SMEM_BYTES>>>(out);
}

// round 15
// speedup vs baseline: 3.6374x; 1.0383x over previous
#include <cuda_runtime.h>
#include <cuda_fp16.h>
#include <cstdint>

#define DM   1024
#define SEQ  2048
#define BATCH 4
#define NH   16
#define DH   64

// Scratch (allocation-free)
__device__ __align__(16) __half g_Xq_h[BATCH * SEQ * DM];    // query in fp16
__device__ __align__(16) __half g_Xkv_h[BATCH * SEQ * DM];   // key_value in fp16
__device__ __align__(16) __half g_Wh[4 * DM * DM];           // Wq,Wk,Wv,Wo fp16
__device__ __align__(16) __half g_Qh[BATCH * NH * SEQ * DH]; // [B,H,S,Dh], pre-scaled
__device__ __align__(16) __half g_Kh[BATCH * NH * SEQ * DH];
__device__ __align__(16) __half g_Vh[BATCH * NH * SEQ * DH];
__device__ __align__(16) __half g_Oh[BATCH * SEQ * DM];      // attn out [B,S,D] fp16

// ============================================================================
// Helpers
// ============================================================================
__device__ __forceinline__ uint32_t smem_u32(const void* p) {
    uint32_t a;
    asm("{ .reg .u64 t; cvta.to.shared.u64 t, %1; cvt.u32.u64 %0, t; }" : "=r"(a) : "l"(p));
    return a;
}

#define MMA_F16(d, a, b0v, b1v)                                                \
    asm volatile("mma.sync.aligned.m16n8k16.row.col.f32.f16.f16.f32 "          \
                 "{%0,%1,%2,%3}, {%4,%5,%6,%7}, {%8,%9}, {%0,%1,%2,%3};"       \
                 : "+f"((d)[0]), "+f"((d)[1]), "+f"((d)[2]), "+f"((d)[3])      \
                 : "r"((a)[0]), "r"((a)[1]), "r"((a)[2]), "r"((a)[3]),         \
                   "r"(b0v), "r"(b1v))

#define LDSM_X4(d, addr)                                                       \
    asm volatile("ldmatrix.sync.aligned.m8n8.x4.shared.b16 {%0,%1,%2,%3}, [%4];" \
                 : "=r"((d)[0]), "=r"((d)[1]), "=r"((d)[2]), "=r"((d)[3])      \
                 : "r"(addr))

#define LDSM_X4_T(d, addr)                                                     \
    asm volatile("ldmatrix.sync.aligned.m8n8.x4.trans.shared.b16 {%0,%1,%2,%3}, [%4];" \
                 : "=r"((d)[0]), "=r"((d)[1]), "=r"((d)[2]), "=r"((d)[3])      \
                 : "r"(addr))

#define CP_ASYNC16(saddr, gptr)                                                \
    asm volatile("cp.async.cg.shared.global [%0], [%1], 16;"                   \
                 :: "r"(saddr), "l"(gptr))
#define CP_COMMIT() asm volatile("cp.async.commit_group;" ::: "memory")
#define CP_WAIT0()  asm volatile("cp.async.wait_group 0;" ::: "memory")
#define CP_WAIT1()  asm volatile("cp.async.wait_group 1;" ::: "memory")

// ============================================================================
// Fused fp32 -> fp16 conversion (single launch; grid exactly covers all data)
// ============================================================================
#define N8X (BATCH * SEQ * DM / 8)   // 1,048,576 per input tensor
#define N8W (DM * DM / 8)            // 131,072 per weight

__global__ void __launch_bounds__(256) f2h_all(const float* __restrict__ q,
                                               const float* __restrict__ kv,
                                               const float* __restrict__ w0,
                                               const float* __restrict__ w1,
                                               const float* __restrict__ w2,
                                               const float* __restrict__ w3) {
    const int i = blockIdx.x * 256 + threadIdx.x;
    const float* src;
    __half* dst;
    int j;
    if (i < N8X) {
        src = q; dst = g_Xq_h; j = i;
    } else if (i < 2 * N8X) {
        src = kv; dst = g_Xkv_h; j = i - 2 * N8X + N8X;
    } else {
        const int k = i - 2 * N8X;
        const int w = k >> 17;            // / N8W
        j = k & (N8W - 1);
        src = (w == 0) ? w0 : (w == 1) ? w1 : (w == 2) ? w2 : w3;
        dst = g_Wh + (size_t)w * DM * DM;
    }
    float4 a = ((const float4*)src)[2 * j];
    float4 b = ((const float4*)src)[2 * j + 1];
    __half2 h0 = __floats2half2_rn(a.x, a.y);
    __half2 h1 = __floats2half2_rn(a.z, a.w);
    __half2 h2 = __floats2half2_rn(b.x, b.y);
    __half2 h3 = __floats2half2_rn(b.z, b.w);
    uint4 o;
    o.x = *(uint32_t*)&h0; o.y = *(uint32_t*)&h1;
    o.z = *(uint32_t*)&h2; o.w = *(uint32_t*)&h3;
    ((uint4*)dst)[j] = o;
}

// ============================================================================
// fp16 GEMM: CTA 128x128, 4 warps, warp 64x64, K-chunk 64, XOR-chunk swizzle.
// 2-stage cp.async (64 KB smem) -> 3 CTAs/SM (12 warps).
// ============================================================================
#define HSTAGE (128 * 128)
#define STAGE_BYTES (2 * HSTAGE)
#define GEMM_SMEM_BYTES (2 * STAGE_BYTES)    // 64 KB
#define NCHUNK 16

__device__ __forceinline__ void gemm_issue_stage_h(const __half* __restrict__ Ablk,
                                                   const __half* __restrict__ Wblk,
                                                   uint32_t dst, int kbase,
                                                   int lr8, int lch) {
#pragma unroll
    for (int it = 0; it < 8; it++) {
        const int row = it * 16 + lr8;
        const uint32_t off = (uint32_t)(row * 128 + ((lch ^ (row & 7)) << 4));
        CP_ASYNC16(dst + off, Ablk + (size_t)row * DM + kbase + lch * 8);
        CP_ASYNC16(dst + HSTAGE + off, Wblk + (size_t)row * DM + kbase + lch * 8);
    }
}

__device__ __forceinline__ void gemm_mainloop_h(const __half* __restrict__ Ablk,
                                                const __half* __restrict__ Wblk,
                                                uint32_t* smg,
                                                float (*acc)[8][4],
                                                int tid) {
    const int lane = tid & 31;
    const int wid = tid >> 5;
    const int wm = (wid & 1) << 6;
    const int wn = (wid >> 1) << 6;
    const int mat = lane >> 3, lrow = lane & 7;
    const int a_row = wm + ((mat & 1) << 3) + lrow;
    const int sel_a = mat >> 1;
    const int b_row = wn + ((mat >> 1) << 3) + lrow;
    const int sel_b = mat & 1;
    const uint32_t smb = smem_u32(smg);

    const int lr8 = tid >> 3;
    const int lch = tid & 7;

#pragma unroll
    for (int mt = 0; mt < 4; mt++)
#pragma unroll
        for (int nt = 0; nt < 8; nt++)
#pragma unroll
            for (int e = 0; e < 4; e++) acc[mt][nt][e] = 0.0f;

    // prologue: both buffers
#pragma unroll
    for (int s = 0; s < 2; s++) {
        gemm_issue_stage_h(Ablk, Wblk, smb + (uint32_t)s * STAGE_BYTES, s * 64, lr8, lch);
        CP_COMMIT();
    }

#pragma unroll 1
    for (int c = 0; c < NCHUNK; c++) {
        CP_WAIT1();                 // stage c resident
        __syncthreads();            // visible to all warps

        const uint32_t asb = smb + (uint32_t)(c & 1) * STAGE_BYTES;
        const uint32_t wsb = asb + HSTAGE;
#pragma unroll
        for (int ks = 0; ks < 4; ks++) {
            uint32_t af[4][4], bf[4][4];
#pragma unroll
            for (int mt = 0; mt < 4; mt++)
                LDSM_X4(af[mt], asb + (uint32_t)((a_row + mt * 16) * 128 +
                                                 (((ks * 2 + sel_a) ^ lrow) << 4)));
#pragma unroll
            for (int p = 0; p < 4; p++)
                LDSM_X4(bf[p], wsb + (uint32_t)((b_row + p * 16) * 128 +
                                                (((ks * 2 + sel_b) ^ lrow) << 4)));
#pragma unroll
            for (int p = 0; p < 4; p++) {
#pragma unroll
                for (int mt = 0; mt < 4; mt++) {
                    MMA_F16(acc[mt][2 * p],     af[mt], bf[p][0], bf[p][1]);
                    MMA_F16(acc[mt][2 * p + 1], af[mt], bf[p][2], bf[p][3]);
                }
            }
        }

        __syncthreads();            // all warps done reading buffer (c&1)
        if (c + 2 < NCHUNK)
            gemm_issue_stage_h(Ablk, Wblk, smb + (uint32_t)(c & 1) * STAGE_BYTES,
                               (c + 2) * 64, lr8, lch);
        CP_COMMIT();                // commit every iter so wait1 semantics hold
    }
}

__global__ void __launch_bounds__(128, 3) qkv_gemm_h(int unused) {
    extern __shared__ uint32_t smg[];
    const int bz = blockIdx.z;
    const __half* A = (bz == 0) ? g_Xq_h : g_Xkv_h;
    const __half* W = g_Wh + (size_t)bz * DM * DM;
    __half* out    = (bz == 0) ? g_Qh : ((bz == 1) ? g_Kh : g_Vh);
    const float scale = (bz == 0) ? 0.125f : 1.0f;

    const int m0 = blockIdx.y * 128;
    const int n0 = blockIdx.x * 128;
    const int tid = threadIdx.x;
    const int lane = tid & 31, wid = tid >> 5;
    const int wm = (wid & 1) << 6, wn = (wid >> 1) << 6;
    const int r = lane >> 2, cl = lane & 3;

    float acc[4][8][4];
    gemm_mainloop_h(A + (size_t)m0 * DM, W + (size_t)n0 * DM, smg, acc, tid);

#pragma unroll
    for (int mt = 0; mt < 4; mt++) {
#pragma unroll
        for (int nt = 0; nt < 8; nt++) {
            const int mr = m0 + wm + mt * 16 + r;
            const int nc = n0 + wn + nt * 8 + 2 * cl;
            const int b = mr >> 11, s = mr & 2047;
            const int h = nc >> 6, dh = nc & 63;
            __half2 h0 = __floats2half2_rn(acc[mt][nt][0] * scale, acc[mt][nt][1] * scale);
            __half2 h1 = __floats2half2_rn(acc[mt][nt][2] * scale, acc[mt][nt][3] * scale);
            *(__half2*)(out + (((size_t)(b * NH + h) * SEQ + s) * DH + dh)) = h0;
            *(__half2*)(out + (((size_t)(b * NH + h) * SEQ + (s + 8)) * DH + dh)) = h1;
        }
    }
}

__global__ void __launch_bounds__(128, 3) proj_gemm_h(float* __restrict__ C) {
    extern __shared__ uint32_t smg[];
    const int m0 = blockIdx.y * 128;
    const int n0 = blockIdx.x * 128;
    const int tid = threadIdx.x;
    const int lane = tid & 31, wid = tid >> 5;
    const int wm = (wid & 1) << 6, wn = (wid >> 1) << 6;
    const int r = lane >> 2, cl = lane & 3;

    float acc[4][8][4];
    gemm_mainloop_h(g_Oh + (size_t)m0 * DM, g_Wh + (size_t)3 * DM * DM + (size_t)n0 * DM,
                    smg, acc, tid);

#pragma unroll
    for (int mt = 0; mt < 4; mt++) {
#pragma unroll
        for (int nt = 0; nt < 8; nt++) {
            const int mr = m0 + wm + mt * 16 + r;
            const int nc = n0 + wn + nt * 8 + 2 * cl;
            *(float2*)&C[(size_t)mr * DM + nc] = make_float2(acc[mt][nt][0], acc[mt][nt][1]);
            *(float2*)&C[(size_t)(mr + 8) * DM + nc] = make_float2(acc[mt][nt][2], acc[mt][nt][3]);
        }
    }
}

// ============================================================================
// Flash attention (R14-validated, unchanged): fp16 mma + ldmatrix; cp.async
// double-buffered K/V; V row-major with ldmatrix.trans for PV.
// ============================================================================
#define AQ_B 0
#define AP_B 16384
#define AKV_B 32768
#define ATTN_SMEM_BYTES 65536

__global__ void __launch_bounds__(256) attn_mma() {
    extern __shared__ uint32_t sm4[];

    const int tid = threadIdx.x;
    const int wid = tid >> 5, lane = tid & 31;
    const int r = lane >> 2, cl = lane & 3;
    const int mat = lane >> 3, lrow = lane & 7;
    const int qt = (int)(gridDim.x - 1) - (int)blockIdx.x;   // heavy first
    const int bh = blockIdx.y;
    const int q0 = qt * 128;
    const int wq = wid * 16;
    const size_t base = (size_t)bh * SEQ * DH;

    const uint32_t smb = smem_u32(sm4);
    const uint32_t Qs_b = smb + AQ_B;
    const uint32_t Ps_b = smb + AP_B;

    const int a_off = ((mat & 1) << 3) + lrow;
    const int sel_a = mat >> 1;
    const int b_off = ((mat >> 1) << 3) + lrow;
    const int sel_b = mat & 1;

    const int ld_row = tid >> 3;
    const int ld_ch = tid & 7;

    // Load Q tile (128 x 64 fp16), XOR swizzle
#pragma unroll
    for (int it = 0; it < 4; it++) {
        const int id = it * 256 + tid;
        const int row = id >> 3, ch = id & 7;
        uint4 v = *(const uint4*)(g_Qh + base + (size_t)(q0 + row) * DH + ch * 8);
        *(uint4*)((char*)sm4 + row * 128 + ((ch ^ (row & 7)) << 4)) = v;
    }

    float o[8][4];
#pragma unroll
    for (int nf = 0; nf < 8; nf++)
#pragma unroll
        for (int e = 0; e < 4; e++) o[nf][e] = 0.0f;
    float m0v = -1e30f, m1v = -1e30f, l0v = 0.0f, l1v = 0.0f;

    const int ntiles = 2 * qt + 2;

    // Prologue: issue K/V tile 0 into buffer 0
    {
        const uint32_t kb = smb + AKV_B;
#pragma unroll
        for (int it = 0; it < 2; it++) {
            const int row = it * 32 + ld_row;
            const uint32_t off = (uint32_t)(row * 128 + ((ld_ch ^ (row & 7)) << 4));
            CP_ASYNC16(kb + off, g_Kh + base + (size_t)row * DH + ld_ch * 8);
            CP_ASYNC16(kb + 8192 + off, g_Vh + base + (size_t)row * DH + ld_ch * 8);
        }
        CP_COMMIT();
    }

#pragma unroll 1
    for (int t = 0; t < ntiles; t++) {
        const int k0g = t * 64;
        CP_WAIT0();
        __syncthreads();

        if (t + 1 < ntiles) {
            const uint32_t kb = smb + AKV_B + (uint32_t)((t + 1) & 1) * 16384;
            const int kn = (t + 1) * 64;
#pragma unroll
            for (int it = 0; it < 2; it++) {
                const int row = it * 32 + ld_row;
                const uint32_t off = (uint32_t)(row * 128 + ((ld_ch ^ (row & 7)) << 4));
                CP_ASYNC16(kb + off, g_Kh + base + (size_t)(kn + row) * DH + ld_ch * 8);
                CP_ASYNC16(kb + 8192 + off, g_Vh + base + (size_t)(kn + row) * DH + ld_ch * 8);
            }
        }
        CP_COMMIT();

        const uint32_t Ks_b = smb + AKV_B + (uint32_t)(t & 1) * 16384;
        const uint32_t Vs_b = Ks_b + 8192;

        // Scores
        float sfr[8][4];
#pragma unroll
        for (int nf = 0; nf < 8; nf++)
#pragma unroll
            for (int e = 0; e < 4; e++) sfr[nf][e] = 0.0f;
#pragma unroll
        for (int kc = 0; kc < 4; kc++) {
            uint32_t af[4], bf[4][4];
            LDSM_X4(af, Qs_b + (uint32_t)((wq + a_off) * 128 +
                                          (((kc * 2 + sel_a) ^ lrow) << 4)));
#pragma unroll
            for (int p = 0; p < 4; p++)
                LDSM_X4(bf[p], Ks_b + (uint32_t)((p * 16 + b_off) * 128 +
                                                 (((kc * 2 + sel_b) ^ lrow) << 4)));
#pragma unroll
            for (int p = 0; p < 4; p++) {
                MMA_F16(sfr[2 * p],     af, bf[p][0], bf[p][1]);
                MMA_F16(sfr[2 * p + 1], af, bf[p][2], bf[p][3]);
            }
        }

        // Causal mask (only diagonal-overlap tiles)
        if (t >= 2 * qt) {
            const int row0 = q0 + wq + r, row1 = row0 + 8;
#pragma unroll
            for (int nf = 0; nf < 8; nf++) {
                const int c0 = k0g + nf * 8 + 2 * cl;
                if (c0 > row0) sfr[nf][0] = -1e30f;
                if (c0 + 1 > row0) sfr[nf][1] = -1e30f;
                if (c0 > row1) sfr[nf][2] = -1e30f;
                if (c0 + 1 > row1) sfr[nf][3] = -1e30f;
            }
        }

        // Online softmax
        float mx0 = -1e30f, mx1 = -1e30f;
#pragma unroll
        for (int nf = 0; nf < 8; nf++) {
            mx0 = fmaxf(mx0, fmaxf(sfr[nf][0], sfr[nf][1]));
            mx1 = fmaxf(mx1, fmaxf(sfr[nf][2], sfr[nf][3]));
        }
        mx0 = fmaxf(mx0, __shfl_xor_sync(0xffffffffu, mx0, 1));
        mx0 = fmaxf(mx0, __shfl_xor_sync(0xffffffffu, mx0, 2));
        mx1 = fmaxf(mx1, __shfl_xor_sync(0xffffffffu, mx1, 1));
        mx1 = fmaxf(mx1, __shfl_xor_sync(0xffffffffu, mx1, 2));
        const float mn0 = fmaxf(m0v, mx0), mn1 = fmaxf(m1v, mx1);
        const float a0 = __expf(m0v - mn0), a1 = __expf(m1v - mn1);
        float rs0 = 0.0f, rs1 = 0.0f;
        uint32_t* prow0 = sm4 + AP_B / 4 + (wq + r) * 32 + cl;
        uint32_t* prow1 = prow0 + 256;
#pragma unroll
        for (int nf = 0; nf < 8; nf++) {
            const float p0 = __expf(sfr[nf][0] - mn0);
            const float p1 = __expf(sfr[nf][1] - mn0);
            const float p2 = __expf(sfr[nf][2] - mn1);
            const float p3 = __expf(sfr[nf][3] - mn1);
            rs0 += p0 + p1;
            rs1 += p2 + p3;
            __half2 hp0 = __floats2half2_rn(p0, p1);
            __half2 hp1 = __floats2half2_rn(p2, p3);
            prow0[(nf ^ r) << 2] = *(uint32_t*)&hp0;
            prow1[(nf ^ r) << 2] = *(uint32_t*)&hp1;
        }
        rs0 += __shfl_xor_sync(0xffffffffu, rs0, 1);
        rs0 += __shfl_xor_sync(0xffffffffu, rs0, 2);
        rs1 += __shfl_xor_sync(0xffffffffu, rs1, 1);
        rs1 += __shfl_xor_sync(0xffffffffu, rs1, 2);
        l0v = l0v * a0 + rs0;
        l1v = l1v * a1 + rs1;
        m0v = mn0;
        m1v = mn1;
#pragma unroll
        for (int nf = 0; nf < 8; nf++) {
            o[nf][0] *= a0;
            o[nf][1] *= a0;
            o[nf][2] *= a1;
            o[nf][3] *= a1;
        }
        __syncwarp();

        // O += P . V (V row-major, trans ldmatrix)
#pragma unroll
        for (int kc = 0; kc < 4; kc++) {
            uint32_t af[4], bf[4][4];
            LDSM_X4(af, Ps_b + (uint32_t)((wq + a_off) * 128 +
                                          (((kc * 2 + sel_a) ^ lrow) << 4)));
            const int vrow = kc * 16 + a_off;
#pragma unroll
            for (int p = 0; p < 4; p++)
                LDSM_X4_T(bf[p], Vs_b + (uint32_t)(vrow * 128 +
                                                   (((2 * p + sel_a) ^ lrow) << 4)));
#pragma unroll
            for (int p = 0; p < 4; p++) {
                MMA_F16(o[2 * p],     af, bf[p][0], bf[p][1]);
                MMA_F16(o[2 * p + 1], af, bf[p][2], bf[p][3]);
            }
        }
    }

    // Epilogue: normalize, write g_Oh [B,S,D] fp16
    const float i0 = 1.0f / l0v, i1 = 1.0f / l1v;
    const int b = bh >> 4, h = bh & 15;
    const int row0 = q0 + wq + r, row1 = row0 + 8;
#pragma unroll
    for (int nf = 0; nf < 8; nf++) {
        const int col = h * DH + nf * 8 + 2 * cl;
        __half2 w0 = __floats2half2_rn(o[nf][0] * i0, o[nf][1] * i0);
        __half2 w1 = __floats2half2_rn(o[nf][2] * i1, o[nf][3] * i1);
        *(__half2*)(g_Oh + (size_t)(b * SEQ + row0) * DM + col) = w0;
        *(__half2*)(g_Oh + (size_t)(b * SEQ + row1) * DM + col) = w1;
    }
}

// ============================================================================
// Launch
// ============================================================================
extern "C" void kernel_launch(void* const* d_in, const int* in_sizes, int n_in,
                              void* d_out, int out_size) {
    const float* q  = (const float*)d_in[0];
    const float* kv = (const float*)d_in[1];
    const float* Wq = (const float*)d_in[2];
    const float* Wk = (const float*)d_in[3];
    const float* Wv = (const float*)d_in[4];
    const float* Wo = (const float*)d_in[5];
    float* out = (float*)d_out;

    cudaFuncSetAttribute(qkv_gemm_h, cudaFuncAttributeMaxDynamicSharedMemorySize,
                         GEMM_SMEM_BYTES);
    cudaFuncSetAttribute(proj_gemm_h, cudaFuncAttributeMaxDynamicSharedMemorySize,
                         GEMM_SMEM_BYTES);
    cudaFuncSetAttribute(attn_mma, cudaFuncAttributeMaxDynamicSharedMemorySize,
                         ATTN_SMEM_BYTES);

    // 1) Convert inputs + weights to fp16 (single launch)
    f2h_all<<<(2 * N8X + 4 * N8W) / 256, 256>>>(q, kv, Wq, Wk, Wv, Wo);

    // 2) QKV projections -> [B,H,S,Dh] fp16
    qkv_gemm_h<<<dim3(DM / 128, (BATCH * SEQ) / 128, 3), 128, GEMM_SMEM_BYTES>>>(0);

    // 3) Causal flash attention -> g_Oh
    attn_mma<<<dim3(SEQ / 128, BATCH * NH), 256, ATTN_SMEM_BYTES>>>();

    // 4) Output projection -> d_out fp32
    proj_gemm_h<<<dim3(DM / 128, (BATCH * SEQ) / 128), 128, GEMM_SMEM_BYTES>>>(out);
}

// round 16
// speedup vs baseline: 3.6620x; 1.0068x over previous
#include <cuda_runtime.h>
#include <cuda_fp16.h>
#include <cstdint>

#define DM   1024
#define SEQ  2048
#define BATCH 4
#define NH   16
#define DH   64

// Scratch (allocation-free)
__device__ __align__(16) __half g_Xq_h[BATCH * SEQ * DM];    // query in fp16
__device__ __align__(16) __half g_Xkv_h[BATCH * SEQ * DM];   // key_value in fp16
__device__ __align__(16) __half g_Wh[4 * DM * DM];           // Wq,Wk,Wv,Wo fp16
__device__ __align__(16) __half g_Qh[BATCH * NH * SEQ * DH]; // [B,H,S,Dh], pre-scaled
__device__ __align__(16) __half g_Kh[BATCH * NH * SEQ * DH];
__device__ __align__(16) __half g_Vh[BATCH * NH * SEQ * DH];
__device__ __align__(16) __half g_Oh[BATCH * SEQ * DM];      // attn out [B,S,D] fp16

// ============================================================================
// Helpers
// ============================================================================
__device__ __forceinline__ uint32_t smem_u32(const void* p) {
    uint32_t a;
    asm("{ .reg .u64 t; cvta.to.shared.u64 t, %1; cvt.u32.u64 %0, t; }" : "=r"(a) : "l"(p));
    return a;
}

#define MMA_F16(d, a, b0v, b1v)                                                \
    asm volatile("mma.sync.aligned.m16n8k16.row.col.f32.f16.f16.f32 "          \
                 "{%0,%1,%2,%3}, {%4,%5,%6,%7}, {%8,%9}, {%0,%1,%2,%3};"       \
                 : "+f"((d)[0]), "+f"((d)[1]), "+f"((d)[2]), "+f"((d)[3])      \
                 : "r"((a)[0]), "r"((a)[1]), "r"((a)[2]), "r"((a)[3]),         \
                   "r"(b0v), "r"(b1v))

#define LDSM_X4(d, addr)                                                       \
    asm volatile("ldmatrix.sync.aligned.m8n8.x4.shared.b16 {%0,%1,%2,%3}, [%4];" \
                 : "=r"((d)[0]), "=r"((d)[1]), "=r"((d)[2]), "=r"((d)[3])      \
                 : "r"(addr))

#define LDSM_X4_T(d, addr)                                                     \
    asm volatile("ldmatrix.sync.aligned.m8n8.x4.trans.shared.b16 {%0,%1,%2,%3}, [%4];" \
                 : "=r"((d)[0]), "=r"((d)[1]), "=r"((d)[2]), "=r"((d)[3])      \
                 : "r"(addr))

#define CP_ASYNC16(saddr, gptr)                                                \
    asm volatile("cp.async.cg.shared.global [%0], [%1], 16;"                   \
                 :: "r"(saddr), "l"(gptr))
#define CP_COMMIT() asm volatile("cp.async.commit_group;" ::: "memory")
#define CP_WAIT0()  asm volatile("cp.async.wait_group 0;" ::: "memory")
#define CP_WAIT1()  asm volatile("cp.async.wait_group 1;" ::: "memory")

// ============================================================================
// Fused fp32 -> fp16 conversion (single launch; R15-validated)
// ============================================================================
#define N8X (BATCH * SEQ * DM / 8)
#define N8W (DM * DM / 8)

__global__ void __launch_bounds__(256) f2h_all(const float* __restrict__ q,
                                               const float* __restrict__ kv,
                                               const float* __restrict__ w0,
                                               const float* __restrict__ w1,
                                               const float* __restrict__ w2,
                                               const float* __restrict__ w3) {
    const int i = blockIdx.x * 256 + threadIdx.x;
    const float* src;
    __half* dst;
    int j;
    if (i < N8X) {
        src = q; dst = g_Xq_h; j = i;
    } else if (i < 2 * N8X) {
        src = kv; dst = g_Xkv_h; j = i - N8X;
    } else {
        const int k = i - 2 * N8X;
        const int w = k >> 17;
        j = k & (N8W - 1);
        src = (w == 0) ? w0 : (w == 1) ? w1 : (w == 2) ? w2 : w3;
        dst = g_Wh + (size_t)w * DM * DM;
    }
    float4 a = ((const float4*)src)[2 * j];
    float4 b = ((const float4*)src)[2 * j + 1];
    __half2 h0 = __floats2half2_rn(a.x, a.y);
    __half2 h1 = __floats2half2_rn(a.z, a.w);
    __half2 h2 = __floats2half2_rn(b.x, b.y);
    __half2 h3 = __floats2half2_rn(b.z, b.w);
    uint4 o;
    o.x = *(uint32_t*)&h0; o.y = *(uint32_t*)&h1;
    o.z = *(uint32_t*)&h2; o.w = *(uint32_t*)&h3;
    ((uint4*)dst)[j] = o;
}

// ============================================================================
// fp16 GEMM (R15-validated, unchanged): CTA 128x128, warp 64x64, K-chunk 64,
// 2-stage cp.async (64 KB) -> 3 CTAs/SM.
// ============================================================================
#define HSTAGE (128 * 128)
#define STAGE_BYTES (2 * HSTAGE)
#define GEMM_SMEM_BYTES (2 * STAGE_BYTES)
#define NCHUNK 16

__device__ __forceinline__ void gemm_issue_stage_h(const __half* __restrict__ Ablk,
                                                   const __half* __restrict__ Wblk,
                                                   uint32_t dst, int kbase,
                                                   int lr8, int lch) {
#pragma unroll
    for (int it = 0; it < 8; it++) {
        const int row = it * 16 + lr8;
        const uint32_t off = (uint32_t)(row * 128 + ((lch ^ (row & 7)) << 4));
        CP_ASYNC16(dst + off, Ablk + (size_t)row * DM + kbase + lch * 8);
        CP_ASYNC16(dst + HSTAGE + off, Wblk + (size_t)row * DM + kbase + lch * 8);
    }
}

__device__ __forceinline__ void gemm_mainloop_h(const __half* __restrict__ Ablk,
                                                const __half* __restrict__ Wblk,
                                                uint32_t* smg,
                                                float (*acc)[8][4],
                                                int tid) {
    const int lane = tid & 31;
    const int wid = tid >> 5;
    const int wm = (wid & 1) << 6;
    const int wn = (wid >> 1) << 6;
    const int mat = lane >> 3, lrow = lane & 7;
    const int a_row = wm + ((mat & 1) << 3) + lrow;
    const int sel_a = mat >> 1;
    const int b_row = wn + ((mat >> 1) << 3) + lrow;
    const int sel_b = mat & 1;
    const uint32_t smb = smem_u32(smg);

    const int lr8 = tid >> 3;
    const int lch = tid & 7;

#pragma unroll
    for (int mt = 0; mt < 4; mt++)
#pragma unroll
        for (int nt = 0; nt < 8; nt++)
#pragma unroll
            for (int e = 0; e < 4; e++) acc[mt][nt][e] = 0.0f;

#pragma unroll
    for (int s = 0; s < 2; s++) {
        gemm_issue_stage_h(Ablk, Wblk, smb + (uint32_t)s * STAGE_BYTES, s * 64, lr8, lch);
        CP_COMMIT();
    }

#pragma unroll 1
    for (int c = 0; c < NCHUNK; c++) {
        CP_WAIT1();
        __syncthreads();

        const uint32_t asb = smb + (uint32_t)(c & 1) * STAGE_BYTES;
        const uint32_t wsb = asb + HSTAGE;
#pragma unroll
        for (int ks = 0; ks < 4; ks++) {
            uint32_t af[4][4], bf[4][4];
#pragma unroll
            for (int mt = 0; mt < 4; mt++)
                LDSM_X4(af[mt], asb + (uint32_t)((a_row + mt * 16) * 128 +
                                                 (((ks * 2 + sel_a) ^ lrow) << 4)));
#pragma unroll
            for (int p = 0; p < 4; p++)
                LDSM_X4(bf[p], wsb + (uint32_t)((b_row + p * 16) * 128 +
                                                (((ks * 2 + sel_b) ^ lrow) << 4)));
#pragma unroll
            for (int p = 0; p < 4; p++) {
#pragma unroll
                for (int mt = 0; mt < 4; mt++) {
                    MMA_F16(acc[mt][2 * p],     af[mt], bf[p][0], bf[p][1]);
                    MMA_F16(acc[mt][2 * p + 1], af[mt], bf[p][2], bf[p][3]);
                }
            }
        }

        __syncthreads();
        if (c + 2 < NCHUNK)
            gemm_issue_stage_h(Ablk, Wblk, smb + (uint32_t)(c & 1) * STAGE_BYTES,
                               (c + 2) * 64, lr8, lch);
        CP_COMMIT();
    }
}

__global__ void __launch_bounds__(128, 3) qkv_gemm_h(int unused) {
    extern __shared__ uint32_t smg[];
    const int bz = blockIdx.z;
    const __half* A = (bz == 0) ? g_Xq_h : g_Xkv_h;
    const __half* W = g_Wh + (size_t)bz * DM * DM;
    __half* out    = (bz == 0) ? g_Qh : ((bz == 1) ? g_Kh : g_Vh);
    const float scale = (bz == 0) ? 0.125f : 1.0f;

    const int m0 = blockIdx.y * 128;
    const int n0 = blockIdx.x * 128;
    const int tid = threadIdx.x;
    const int lane = tid & 31, wid = tid >> 5;
    const int wm = (wid & 1) << 6, wn = (wid >> 1) << 6;
    const int r = lane >> 2, cl = lane & 3;

    float acc[4][8][4];
    gemm_mainloop_h(A + (size_t)m0 * DM, W + (size_t)n0 * DM, smg, acc, tid);

#pragma unroll
    for (int mt = 0; mt < 4; mt++) {
#pragma unroll
        for (int nt = 0; nt < 8; nt++) {
            const int mr = m0 + wm + mt * 16 + r;
            const int nc = n0 + wn + nt * 8 + 2 * cl;
            const int b = mr >> 11, s = mr & 2047;
            const int h = nc >> 6, dh = nc & 63;
            __half2 h0 = __floats2half2_rn(acc[mt][nt][0] * scale, acc[mt][nt][1] * scale);
            __half2 h1 = __floats2half2_rn(acc[mt][nt][2] * scale, acc[mt][nt][3] * scale);
            *(__half2*)(out + (((size_t)(b * NH + h) * SEQ + s) * DH + dh)) = h0;
            *(__half2*)(out + (((size_t)(b * NH + h) * SEQ + (s + 8)) * DH + dh)) = h1;
        }
    }
}

__global__ void __launch_bounds__(128, 3) proj_gemm_h(float* __restrict__ C) {
    extern __shared__ uint32_t smg[];
    const int m0 = blockIdx.y * 128;
    const int n0 = blockIdx.x * 128;
    const int tid = threadIdx.x;
    const int lane = tid & 31, wid = tid >> 5;
    const int wm = (wid & 1) << 6, wn = (wid >> 1) << 6;
    const int r = lane >> 2, cl = lane & 3;

    float acc[4][8][4];
    gemm_mainloop_h(g_Oh + (size_t)m0 * DM, g_Wh + (size_t)3 * DM * DM + (size_t)n0 * DM,
                    smg, acc, tid);

#pragma unroll
    for (int mt = 0; mt < 4; mt++) {
#pragma unroll
        for (int nt = 0; nt < 8; nt++) {
            const int mr = m0 + wm + mt * 16 + r;
            const int nc = n0 + wn + nt * 8 + 2 * cl;
            *(float2*)&C[(size_t)mr * DM + nc] = make_float2(acc[mt][nt][0], acc[mt][nt][1]);
            *(float2*)&C[(size_t)(mr + 8) * DM + nc] = make_float2(acc[mt][nt][2], acc[mt][nt][3]);
        }
    }
}

// ============================================================================
// Flash attention: fp16 mma + ldmatrix; cp.async double-buffered K/V;
// Q fragments hoisted out of the tile loop; l-reduction deferred to epilogue.
// BQ=128, BK=64, Dh=64, 256 threads (8 warps x 16 q-rows each).
// ============================================================================
#define AQ_B 0
#define AP_B 16384
#define AKV_B 32768
#define ATTN_SMEM_BYTES 65536

__global__ void __launch_bounds__(256) attn_mma() {
    extern __shared__ uint32_t sm4[];

    const int tid = threadIdx.x;
    const int wid = tid >> 5, lane = tid & 31;
    const int r = lane >> 2, cl = lane & 3;
    const int mat = lane >> 3, lrow = lane & 7;
    const int qt = (int)(gridDim.x - 1) - (int)blockIdx.x;   // heavy first
    const int bh = blockIdx.y;
    const int q0 = qt * 128;
    const int wq = wid * 16;
    const size_t base = (size_t)bh * SEQ * DH;

    const uint32_t smb = smem_u32(sm4);
    const uint32_t Qs_b = smb + AQ_B;
    const uint32_t Ps_b = smb + AP_B;

    const int a_off = ((mat & 1) << 3) + lrow;
    const int sel_a = mat >> 1;
    const int b_off = ((mat >> 1) << 3) + lrow;
    const int sel_b = mat & 1;

    const int ld_row = tid >> 3;
    const int ld_ch = tid & 7;

    // Load Q tile (128 x 64 fp16), XOR swizzle
#pragma unroll
    for (int it = 0; it < 4; it++) {
        const int id = it * 256 + tid;
        const int row = id >> 3, ch = id & 7;
        uint4 v = *(const uint4*)(g_Qh + base + (size_t)(q0 + row) * DH + ch * 8);
        *(uint4*)((char*)sm4 + row * 128 + ((ch ^ (row & 7)) << 4)) = v;
    }

    // Prologue: issue K/V tile 0 into buffer 0
    {
        const uint32_t kb = smb + AKV_B;
#pragma unroll
        for (int it = 0; it < 2; it++) {
            const int row = it * 32 + ld_row;
            const uint32_t off = (uint32_t)(row * 128 + ((ld_ch ^ (row & 7)) << 4));
            CP_ASYNC16(kb + off, g_Kh + base + (size_t)row * DH + ld_ch * 8);
            CP_ASYNC16(kb + 8192 + off, g_Vh + base + (size_t)row * DH + ld_ch * 8);
        }
        CP_COMMIT();
    }

    // Q fragments are tile-invariant: load once.
    __syncthreads();
    uint32_t qf[4][4];
#pragma unroll
    for (int kc = 0; kc < 4; kc++)
        LDSM_X4(qf[kc], Qs_b + (uint32_t)((wq + a_off) * 128 +
                                          (((kc * 2 + sel_a) ^ lrow) << 4)));

    float o[8][4];
#pragma unroll
    for (int nf = 0; nf < 8; nf++)
#pragma unroll
        for (int e = 0; e < 4; e++) o[nf][e] = 0.0f;
    float m0v = -1e30f, m1v = -1e30f;
    float lp0 = 0.0f, lp1 = 0.0f;   // per-thread partial row sums (quad-consistent)

    const int ntiles = 2 * qt + 2;

#pragma unroll 1
    for (int t = 0; t < ntiles; t++) {
        const int k0g = t * 64;
        CP_WAIT0();
        __syncthreads();

        if (t + 1 < ntiles) {
            const uint32_t kb = smb + AKV_B + (uint32_t)((t + 1) & 1) * 16384;
            const int kn = (t + 1) * 64;
#pragma unroll
            for (int it = 0; it < 2; it++) {
                const int row = it * 32 + ld_row;
                const uint32_t off = (uint32_t)(row * 128 + ((ld_ch ^ (row & 7)) << 4));
                CP_ASYNC16(kb + off, g_Kh + base + (size_t)(kn + row) * DH + ld_ch * 8);
                CP_ASYNC16(kb + 8192 + off, g_Vh + base + (size_t)(kn + row) * DH + ld_ch * 8);
            }
        }
        CP_COMMIT();

        const uint32_t Ks_b = smb + AKV_B + (uint32_t)(t & 1) * 16384;
        const uint32_t Vs_b = Ks_b + 8192;

        // Scores (Q fragments from registers)
        float sfr[8][4];
#pragma unroll
        for (int nf = 0; nf < 8; nf++)
#pragma unroll
            for (int e = 0; e < 4; e++) sfr[nf][e] = 0.0f;
#pragma unroll
        for (int kc = 0; kc < 4; kc++) {
            uint32_t bf[4][4];
#pragma unroll
            for (int p = 0; p < 4; p++)
                LDSM_X4(bf[p], Ks_b + (uint32_t)((p * 16 + b_off) * 128 +
                                                 (((kc * 2 + sel_b) ^ lrow) << 4)));
#pragma unroll
            for (int p = 0; p < 4; p++) {
                MMA_F16(sfr[2 * p],     qf[kc], bf[p][0], bf[p][1]);
                MMA_F16(sfr[2 * p + 1], qf[kc], bf[p][2], bf[p][3]);
            }
        }

        // Causal mask (only diagonal-overlap tiles)
        if (t >= 2 * qt) {
            const int row0 = q0 + wq + r, row1 = row0 + 8;
#pragma unroll
            for (int nf = 0; nf < 8; nf++) {
                const int c0 = k0g + nf * 8 + 2 * cl;
                if (c0 > row0) sfr[nf][0] = -1e30f;
                if (c0 + 1 > row0) sfr[nf][1] = -1e30f;
                if (c0 > row1) sfr[nf][2] = -1e30f;
                if (c0 + 1 > row1) sfr[nf][3] = -1e30f;
            }
        }

        // Online softmax (max quad-reduced; l kept as per-thread partial)
        float mx0 = -1e30f, mx1 = -1e30f;
#pragma unroll
        for (int nf = 0; nf < 8; nf++) {
            mx0 = fmaxf(mx0, fmaxf(sfr[nf][0], sfr[nf][1]));
            mx1 = fmaxf(mx1, fmaxf(sfr[nf][2], sfr[nf][3]));
        }
        mx0 = fmaxf(mx0, __shfl_xor_sync(0xffffffffu, mx0, 1));
        mx0 = fmaxf(mx0, __shfl_xor_sync(0xffffffffu, mx0, 2));
        mx1 = fmaxf(mx1, __shfl_xor_sync(0xffffffffu, mx1, 1));
        mx1 = fmaxf(mx1, __shfl_xor_sync(0xffffffffu, mx1, 2));
        const float mn0 = fmaxf(m0v, mx0), mn1 = fmaxf(m1v, mx1);
        const float a0 = __expf(m0v - mn0), a1 = __expf(m1v - mn1);
        float rs0 = 0.0f, rs1 = 0.0f;
        uint32_t* prow0 = sm4 + AP_B / 4 + (wq + r) * 32 + cl;
        uint32_t* prow1 = prow0 + 256;
#pragma unroll
        for (int nf = 0; nf < 8; nf++) {
            const float p0 = __expf(sfr[nf][0] - mn0);
            const float p1 = __expf(sfr[nf][1] - mn0);
            const float p2 = __expf(sfr[nf][2] - mn1);
            const float p3 = __expf(sfr[nf][3] - mn1);
            rs0 += p0 + p1;
            rs1 += p2 + p3;
            __half2 hp0 = __floats2half2_rn(p0, p1);
            __half2 hp1 = __floats2half2_rn(p2, p3);
            prow0[(nf ^ r) << 2] = *(uint32_t*)&hp0;
            prow1[(nf ^ r) << 2] = *(uint32_t*)&hp1;
        }
        lp0 = lp0 * a0 + rs0;   // a0/a1 identical across the quad -> consistent
        lp1 = lp1 * a1 + rs1;
        m0v = mn0;
        m1v = mn1;
#pragma unroll
        for (int nf = 0; nf < 8; nf++) {
            o[nf][0] *= a0;
            o[nf][1] *= a0;
            o[nf][2] *= a1;
            o[nf][3] *= a1;
        }
        __syncwarp();

        // O += P . V (V row-major, trans ldmatrix)
#pragma unroll
        for (int kc = 0; kc < 4; kc++) {
            uint32_t af[4], bf[4][4];
            LDSM_X4(af, Ps_b + (uint32_t)((wq + a_off) * 128 +
                                          (((kc * 2 + sel_a) ^ lrow) << 4)));
            const int vrow = kc * 16 + a_off;
#pragma unroll
            for (int p = 0; p < 4; p++)
                LDSM_X4_T(bf[p], Vs_b + (uint32_t)(vrow * 128 +
                                                   (((2 * p + sel_a) ^ lrow) << 4)));
#pragma unroll
            for (int p = 0; p < 4; p++) {
                MMA_F16(o[2 * p],     af, bf[p][0], bf[p][1]);
                MMA_F16(o[2 * p + 1], af, bf[p][2], bf[p][3]);
            }
        }
    }

    // Final l reduction (once instead of per-tile)
    float l0v = lp0, l1v = lp1;
    l0v += __shfl_xor_sync(0xffffffffu, l0v, 1);
    l0v += __shfl_xor_sync(0xffffffffu, l0v, 2);
    l1v += __shfl_xor_sync(0xffffffffu, l1v, 1);
    l1v += __shfl_xor_sync(0xffffffffu, l1v, 2);

    // Epilogue: normalize, write g_Oh [B,S,D] fp16
    const float i0 = 1.0f / l0v, i1 = 1.0f / l1v;
    const int b = bh >> 4, h = bh & 15;
    const int row0 = q0 + wq + r, row1 = row0 + 8;
#pragma unroll
    for (int nf = 0; nf < 8; nf++) {
        const int col = h * DH + nf * 8 + 2 * cl;
        __half2 w0 = __floats2half2_rn(o[nf][0] * i0, o[nf][1] * i0);
        __half2 w1 = __floats2half2_rn(o[nf][2] * i1, o[nf][3] * i1);
        *(__half2*)(g_Oh + (size_t)(b * SEQ + row0) * DM + col) = w0;
        *(__half2*)(g_Oh + (size_t)(b * SEQ + row1) * DM + col) = w1;
    }
}

// ============================================================================
// Launch
// ============================================================================
extern "C" void kernel_launch(void* const* d_in, const int* in_sizes, int n_in,
                              void* d_out, int out_size) {
    const float* q  = (const float*)d_in[0];
    const float* kv = (const float*)d_in[1];
    const float* Wq = (const float*)d_in[2];
    const float* Wk = (const float*)d_in[3];
    const float* Wv = (const float*)d_in[4];
    const float* Wo = (const float*)d_in[5];
    float* out = (float*)d_out;

    cudaFuncSetAttribute(qkv_gemm_h, cudaFuncAttributeMaxDynamicSharedMemorySize,
                         GEMM_SMEM_BYTES);
    cudaFuncSetAttribute(proj_gemm_h, cudaFuncAttributeMaxDynamicSharedMemorySize,
                         GEMM_SMEM_BYTES);
    cudaFuncSetAttribute(attn_mma, cudaFuncAttributeMaxDynamicSharedMemorySize,
                         ATTN_SMEM_BYTES);

    f2h_all<<<(2 * N8X + 4 * N8W) / 256, 256>>>(q, kv, Wq, Wk, Wv, Wo);
    qkv_gemm_h<<<dim3(DM / 128, (BATCH * SEQ) / 128, 3), 128, GEMM_SMEM_BYTES>>>(0);
    attn_mma<<<dim3(SEQ / 128, BATCH * NH), 256, ATTN_SMEM_BYTES>>>();
    proj_gemm_h<<<dim3(DM / 128, (BATCH * SEQ) / 128), 128, GEMM_SMEM_BYTES>>>(out);
}

// round 17
// speedup vs baseline: 4.0292x; 1.1003x over previous
#include <cuda_runtime.h>
#include <cuda_fp16.h>
#include <cstdint>

#define DM   1024
#define SEQ  2048
#define BATCH 4
#define NH   16
#define DH   64

// Scratch (allocation-free)
__device__ __align__(16) __half g_Xq_h[BATCH * SEQ * DM];    // query in fp16
__device__ __align__(16) __half g_Xkv_h[BATCH * SEQ * DM];   // key_value in fp16
__device__ __align__(16) __half g_Wh[4 * DM * DM];           // Wq,Wk,Wv,Wo fp16
__device__ __align__(16) __half g_Qh[BATCH * NH * SEQ * DH]; // [B,H,S,Dh], pre-scaled
__device__ __align__(16) __half g_Kh[BATCH * NH * SEQ * DH];
__device__ __align__(16) __half g_Vh[BATCH * NH * SEQ * DH];
__device__ __align__(16) __half g_Oh[BATCH * SEQ * DM];      // attn out [B,S,D] fp16

// ============================================================================
// Helpers
// ============================================================================
__device__ __forceinline__ uint32_t smem_u32(const void* p) {
    uint32_t a;
    asm("{ .reg .u64 t; cvta.to.shared.u64 t, %1; cvt.u32.u64 %0, t; }" : "=r"(a) : "l"(p));
    return a;
}

#define MMA_F16(d, a, b0v, b1v)                                                \
    asm volatile("mma.sync.aligned.m16n8k16.row.col.f32.f16.f16.f32 "          \
                 "{%0,%1,%2,%3}, {%4,%5,%6,%7}, {%8,%9}, {%0,%1,%2,%3};"       \
                 : "+f"((d)[0]), "+f"((d)[1]), "+f"((d)[2]), "+f"((d)[3])      \
                 : "r"((a)[0]), "r"((a)[1]), "r"((a)[2]), "r"((a)[3]),         \
                   "r"(b0v), "r"(b1v))

#define LDSM_X4(d, addr)                                                       \
    asm volatile("ldmatrix.sync.aligned.m8n8.x4.shared.b16 {%0,%1,%2,%3}, [%4];" \
                 : "=r"((d)[0]), "=r"((d)[1]), "=r"((d)[2]), "=r"((d)[3])      \
                 : "r"(addr))

#define LDSM_X4_T(d, addr)                                                     \
    asm volatile("ldmatrix.sync.aligned.m8n8.x4.trans.shared.b16 {%0,%1,%2,%3}, [%4];" \
                 : "=r"((d)[0]), "=r"((d)[1]), "=r"((d)[2]), "=r"((d)[3])      \
                 : "r"(addr))

#define CP_ASYNC16(saddr, gptr)                                                \
    asm volatile("cp.async.cg.shared.global [%0], [%1], 16;"                   \
                 :: "r"(saddr), "l"(gptr))
#define CP_COMMIT() asm volatile("cp.async.commit_group;" ::: "memory")
#define CP_WAIT0()  asm volatile("cp.async.wait_group 0;" ::: "memory")
#define CP_WAIT1()  asm volatile("cp.async.wait_group 1;" ::: "memory")

// ============================================================================
// Fused fp32 -> fp16 conversion (single launch; R15-validated)
// ============================================================================
#define N8X (BATCH * SEQ * DM / 8)
#define N8W (DM * DM / 8)

__global__ void __launch_bounds__(256) f2h_all(const float* __restrict__ q,
                                               const float* __restrict__ kv,
                                               const float* __restrict__ w0,
                                               const float* __restrict__ w1,
                                               const float* __restrict__ w2,
                                               const float* __restrict__ w3) {
    const int i = blockIdx.x * 256 + threadIdx.x;
    const float* src;
    __half* dst;
    int j;
    if (i < N8X) {
        src = q; dst = g_Xq_h; j = i;
    } else if (i < 2 * N8X) {
        src = kv; dst = g_Xkv_h; j = i - N8X;
    } else {
        const int k = i - 2 * N8X;
        const int w = k >> 17;
        j = k & (N8W - 1);
        src = (w == 0) ? w0 : (w == 1) ? w1 : (w == 2) ? w2 : w3;
        dst = g_Wh + (size_t)w * DM * DM;
    }
    float4 a = ((const float4*)src)[2 * j];
    float4 b = ((const float4*)src)[2 * j + 1];
    __half2 h0 = __floats2half2_rn(a.x, a.y);
    __half2 h1 = __floats2half2_rn(a.z, a.w);
    __half2 h2 = __floats2half2_rn(b.x, b.y);
    __half2 h3 = __floats2half2_rn(b.z, b.w);
    uint4 o;
    o.x = *(uint32_t*)&h0; o.y = *(uint32_t*)&h1;
    o.z = *(uint32_t*)&h2; o.w = *(uint32_t*)&h3;
    ((uint4*)dst)[j] = o;
}

// ============================================================================
// fp16 GEMM (R15-validated, unchanged): CTA 128x128, warp 64x64, K-chunk 64,
// 2-stage cp.async (64 KB) -> 3 CTAs/SM.
// ============================================================================
#define HSTAGE (128 * 128)
#define STAGE_BYTES (2 * HSTAGE)
#define GEMM_SMEM_BYTES (2 * STAGE_BYTES)
#define NCHUNK 16

__device__ __forceinline__ void gemm_issue_stage_h(const __half* __restrict__ Ablk,
                                                   const __half* __restrict__ Wblk,
                                                   uint32_t dst, int kbase,
                                                   int lr8, int lch) {
#pragma unroll
    for (int it = 0; it < 8; it++) {
        const int row = it * 16 + lr8;
        const uint32_t off = (uint32_t)(row * 128 + ((lch ^ (row & 7)) << 4));
        CP_ASYNC16(dst + off, Ablk + (size_t)row * DM + kbase + lch * 8);
        CP_ASYNC16(dst + HSTAGE + off, Wblk + (size_t)row * DM + kbase + lch * 8);
    }
}

__device__ __forceinline__ void gemm_mainloop_h(const __half* __restrict__ Ablk,
                                                const __half* __restrict__ Wblk,
                                                uint32_t* smg,
                                                float (*acc)[8][4],
                                                int tid) {
    const int lane = tid & 31;
    const int wid = tid >> 5;
    const int wm = (wid & 1) << 6;
    const int wn = (wid >> 1) << 6;
    const int mat = lane >> 3, lrow = lane & 7;
    const int a_row = wm + ((mat & 1) << 3) + lrow;
    const int sel_a = mat >> 1;
    const int b_row = wn + ((mat >> 1) << 3) + lrow;
    const int sel_b = mat & 1;
    const uint32_t smb = smem_u32(smg);

    const int lr8 = tid >> 3;
    const int lch = tid & 7;

#pragma unroll
    for (int mt = 0; mt < 4; mt++)
#pragma unroll
        for (int nt = 0; nt < 8; nt++)
#pragma unroll
            for (int e = 0; e < 4; e++) acc[mt][nt][e] = 0.0f;

#pragma unroll
    for (int s = 0; s < 2; s++) {
        gemm_issue_stage_h(Ablk, Wblk, smb + (uint32_t)s * STAGE_BYTES, s * 64, lr8, lch);
        CP_COMMIT();
    }

#pragma unroll 1
    for (int c = 0; c < NCHUNK; c++) {
        CP_WAIT1();
        __syncthreads();

        const uint32_t asb = smb + (uint32_t)(c & 1) * STAGE_BYTES;
        const uint32_t wsb = asb + HSTAGE;
#pragma unroll
        for (int ks = 0; ks < 4; ks++) {
            uint32_t af[4][4], bf[4][4];
#pragma unroll
            for (int mt = 0; mt < 4; mt++)
                LDSM_X4(af[mt], asb + (uint32_t)((a_row + mt * 16) * 128 +
                                                 (((ks * 2 + sel_a) ^ lrow) << 4)));
#pragma unroll
            for (int p = 0; p < 4; p++)
                LDSM_X4(bf[p], wsb + (uint32_t)((b_row + p * 16) * 128 +
                                                (((ks * 2 + sel_b) ^ lrow) << 4)));
#pragma unroll
            for (int p = 0; p < 4; p++) {
#pragma unroll
                for (int mt = 0; mt < 4; mt++) {
                    MMA_F16(acc[mt][2 * p],     af[mt], bf[p][0], bf[p][1]);
                    MMA_F16(acc[mt][2 * p + 1], af[mt], bf[p][2], bf[p][3]);
                }
            }
        }

        __syncthreads();
        if (c + 2 < NCHUNK)
            gemm_issue_stage_h(Ablk, Wblk, smb + (uint32_t)(c & 1) * STAGE_BYTES,
                               (c + 2) * 64, lr8, lch);
        CP_COMMIT();
    }
}

__global__ void __launch_bounds__(128, 3) qkv_gemm_h(int unused) {
    extern __shared__ uint32_t smg[];
    const int bz = blockIdx.z;
    const __half* A = (bz == 0) ? g_Xq_h : g_Xkv_h;
    const __half* W = g_Wh + (size_t)bz * DM * DM;
    __half* out    = (bz == 0) ? g_Qh : ((bz == 1) ? g_Kh : g_Vh);
    const float scale = (bz == 0) ? 0.125f : 1.0f;

    const int m0 = blockIdx.y * 128;
    const int n0 = blockIdx.x * 128;
    const int tid = threadIdx.x;
    const int lane = tid & 31, wid = tid >> 5;
    const int wm = (wid & 1) << 6, wn = (wid >> 1) << 6;
    const int r = lane >> 2, cl = lane & 3;

    float acc[4][8][4];
    gemm_mainloop_h(A + (size_t)m0 * DM, W + (size_t)n0 * DM, smg, acc, tid);

#pragma unroll
    for (int mt = 0; mt < 4; mt++) {
#pragma unroll
        for (int nt = 0; nt < 8; nt++) {
            const int mr = m0 + wm + mt * 16 + r;
            const int nc = n0 + wn + nt * 8 + 2 * cl;
            const int b = mr >> 11, s = mr & 2047;
            const int h = nc >> 6, dh = nc & 63;
            __half2 h0 = __floats2half2_rn(acc[mt][nt][0] * scale, acc[mt][nt][1] * scale);
            __half2 h1 = __floats2half2_rn(acc[mt][nt][2] * scale, acc[mt][nt][3] * scale);
            *(__half2*)(out + (((size_t)(b * NH + h) * SEQ + s) * DH + dh)) = h0;
            *(__half2*)(out + (((size_t)(b * NH + h) * SEQ + (s + 8)) * DH + dh)) = h1;
        }
    }
}

__global__ void __launch_bounds__(128, 3) proj_gemm_h(float* __restrict__ C) {
    extern __shared__ uint32_t smg[];
    const int m0 = blockIdx.y * 128;
    const int n0 = blockIdx.x * 128;
    const int tid = threadIdx.x;
    const int lane = tid & 31, wid = tid >> 5;
    const int wm = (wid & 1) << 6, wn = (wid >> 1) << 6;
    const int r = lane >> 2, cl = lane & 3;

    float acc[4][8][4];
    gemm_mainloop_h(g_Oh + (size_t)m0 * DM, g_Wh + (size_t)3 * DM * DM + (size_t)n0 * DM,
                    smg, acc, tid);

#pragma unroll
    for (int mt = 0; mt < 4; mt++) {
#pragma unroll
        for (int nt = 0; nt < 8; nt++) {
            const int mr = m0 + wm + mt * 16 + r;
            const int nc = n0 + wn + nt * 8 + 2 * cl;
            *(float2*)&C[(size_t)mr * DM + nc] = make_float2(acc[mt][nt][0], acc[mt][nt][1]);
            *(float2*)&C[(size_t)(mr + 8) * DM + nc] = make_float2(acc[mt][nt][2], acc[mt][nt][3]);
        }
    }
}

// ============================================================================
// Flash attention: fp16 mma; P kept in REGISTERS (accumulator layout == A-frag
// layout identity) -> no P smem, no STS/LDSM round-trip, no syncwarp.
// cp.async double-buffered K/V; V row-major + ldmatrix.trans for PV.
// BQ=128, BK=64, Dh=64, 256 threads (8 warps x 16 q-rows each).
// smem: Q[0,16K) K0[16K,24K) V0[24K,32K) K1[32K,40K) V1[40K,48K)
// ============================================================================
#define AKV_B 16384
#define ATTN_SMEM_BYTES 49152

__global__ void __launch_bounds__(256) attn_mma() {
    extern __shared__ uint32_t sm4[];

    const int tid = threadIdx.x;
    const int wid = tid >> 5, lane = tid & 31;
    const int r = lane >> 2, cl = lane & 3;
    const int mat = lane >> 3, lrow = lane & 7;
    const int qt = (int)(gridDim.x - 1) - (int)blockIdx.x;   // heavy first
    const int bh = blockIdx.y;
    const int q0 = qt * 128;
    const int wq = wid * 16;
    const size_t base = (size_t)bh * SEQ * DH;

    const uint32_t smb = smem_u32(sm4);
    const uint32_t Qs_b = smb;

    const int a_off = ((mat & 1) << 3) + lrow;
    const int sel_a = mat >> 1;
    const int b_off = ((mat >> 1) << 3) + lrow;
    const int sel_b = mat & 1;

    const int ld_row = tid >> 3;
    const int ld_ch = tid & 7;

    // Load Q tile (128 x 64 fp16), XOR swizzle
#pragma unroll
    for (int it = 0; it < 4; it++) {
        const int id = it * 256 + tid;
        const int row = id >> 3, ch = id & 7;
        uint4 v = *(const uint4*)(g_Qh + base + (size_t)(q0 + row) * DH + ch * 8);
        *(uint4*)((char*)sm4 + row * 128 + ((ch ^ (row & 7)) << 4)) = v;
    }

    // Prologue: issue K/V tile 0 into buffer 0
    {
        const uint32_t kb = smb + AKV_B;
#pragma unroll
        for (int it = 0; it < 2; it++) {
            const int row = it * 32 + ld_row;
            const uint32_t off = (uint32_t)(row * 128 + ((ld_ch ^ (row & 7)) << 4));
            CP_ASYNC16(kb + off, g_Kh + base + (size_t)row * DH + ld_ch * 8);
            CP_ASYNC16(kb + 8192 + off, g_Vh + base + (size_t)row * DH + ld_ch * 8);
        }
        CP_COMMIT();
    }

    // Q fragments are tile-invariant: load once.
    __syncthreads();
    uint32_t qf[4][4];
#pragma unroll
    for (int kc = 0; kc < 4; kc++)
        LDSM_X4(qf[kc], Qs_b + (uint32_t)((wq + a_off) * 128 +
                                          (((kc * 2 + sel_a) ^ lrow) << 4)));

    float o[8][4];
#pragma unroll
    for (int nf = 0; nf < 8; nf++)
#pragma unroll
        for (int e = 0; e < 4; e++) o[nf][e] = 0.0f;
    float m0v = -1e30f, m1v = -1e30f;
    float lp0 = 0.0f, lp1 = 0.0f;   // per-thread partial row sums (quad-consistent)

    const int ntiles = 2 * qt + 2;

#pragma unroll 1
    for (int t = 0; t < ntiles; t++) {
        const int k0g = t * 64;
        CP_WAIT0();
        __syncthreads();

        if (t + 1 < ntiles) {
            const uint32_t kb = smb + AKV_B + (uint32_t)((t + 1) & 1) * 16384;
            const int kn = (t + 1) * 64;
#pragma unroll
            for (int it = 0; it < 2; it++) {
                const int row = it * 32 + ld_row;
                const uint32_t off = (uint32_t)(row * 128 + ((ld_ch ^ (row & 7)) << 4));
                CP_ASYNC16(kb + off, g_Kh + base + (size_t)(kn + row) * DH + ld_ch * 8);
                CP_ASYNC16(kb + 8192 + off, g_Vh + base + (size_t)(kn + row) * DH + ld_ch * 8);
            }
        }
        CP_COMMIT();

        const uint32_t Ks_b = smb + AKV_B + (uint32_t)(t & 1) * 16384;
        const uint32_t Vs_b = Ks_b + 8192;

        // Scores (Q fragments from registers)
        float sfr[8][4];
#pragma unroll
        for (int nf = 0; nf < 8; nf++)
#pragma unroll
            for (int e = 0; e < 4; e++) sfr[nf][e] = 0.0f;
#pragma unroll
        for (int kc = 0; kc < 4; kc++) {
            uint32_t bf[4][4];
#pragma unroll
            for (int p = 0; p < 4; p++)
                LDSM_X4(bf[p], Ks_b + (uint32_t)((p * 16 + b_off) * 128 +
                                                 (((kc * 2 + sel_b) ^ lrow) << 4)));
#pragma unroll
            for (int p = 0; p < 4; p++) {
                MMA_F16(sfr[2 * p],     qf[kc], bf[p][0], bf[p][1]);
                MMA_F16(sfr[2 * p + 1], qf[kc], bf[p][2], bf[p][3]);
            }
        }

        // Causal mask (only diagonal-overlap tiles)
        if (t >= 2 * qt) {
            const int row0 = q0 + wq + r, row1 = row0 + 8;
#pragma unroll
            for (int nf = 0; nf < 8; nf++) {
                const int c0 = k0g + nf * 8 + 2 * cl;
                if (c0 > row0) sfr[nf][0] = -1e30f;
                if (c0 + 1 > row0) sfr[nf][1] = -1e30f;
                if (c0 > row1) sfr[nf][2] = -1e30f;
                if (c0 + 1 > row1) sfr[nf][3] = -1e30f;
            }
        }

        // Online softmax (max quad-reduced; l kept as per-thread partial)
        float mx0 = -1e30f, mx1 = -1e30f;
#pragma unroll
        for (int nf = 0; nf < 8; nf++) {
            mx0 = fmaxf(mx0, fmaxf(sfr[nf][0], sfr[nf][1]));
            mx1 = fmaxf(mx1, fmaxf(sfr[nf][2], sfr[nf][3]));
        }
        mx0 = fmaxf(mx0, __shfl_xor_sync(0xffffffffu, mx0, 1));
        mx0 = fmaxf(mx0, __shfl_xor_sync(0xffffffffu, mx0, 2));
        mx1 = fmaxf(mx1, __shfl_xor_sync(0xffffffffu, mx1, 1));
        mx1 = fmaxf(mx1, __shfl_xor_sync(0xffffffffu, mx1, 2));
        const float mn0 = fmaxf(m0v, mx0), mn1 = fmaxf(m1v, mx1);
        const float a0 = __expf(m0v - mn0), a1 = __expf(m1v - mn1);
        float rs0 = 0.0f, rs1 = 0.0f;

        // exp -> P directly as register A-fragments (no smem round-trip):
        // col = nf*8+2cl -> k-chunk kc=nf>>1, halves by nf&1; rows r / r+8.
        uint32_t paf[4][4];
#pragma unroll
        for (int nf = 0; nf < 8; nf++) {
            const float p0 = __expf(sfr[nf][0] - mn0);
            const float p1 = __expf(sfr[nf][1] - mn0);
            const float p2 = __expf(sfr[nf][2] - mn1);
            const float p3 = __expf(sfr[nf][3] - mn1);
            rs0 += p0 + p1;
            rs1 += p2 + p3;
            __half2 hp0 = __floats2half2_rn(p0, p1);
            __half2 hp1 = __floats2half2_rn(p2, p3);
            const int kc = nf >> 1;
            const int hi = (nf & 1) << 1;   // 0 for k-low half, 2 for k-high half
            paf[kc][hi + 0] = *(uint32_t*)&hp0;
            paf[kc][hi + 1] = *(uint32_t*)&hp1;
        }
        lp0 = lp0 * a0 + rs0;
        lp1 = lp1 * a1 + rs1;
        m0v = mn0;
        m1v = mn1;
#pragma unroll
        for (int nf = 0; nf < 8; nf++) {
            o[nf][0] *= a0;
            o[nf][1] *= a0;
            o[nf][2] *= a1;
            o[nf][3] *= a1;
        }

        // O += P . V (P from registers; V row-major, trans ldmatrix)
#pragma unroll
        for (int kc = 0; kc < 4; kc++) {
            uint32_t bf[4][4];
            const int vrow = kc * 16 + a_off;
#pragma unroll
            for (int p = 0; p < 4; p++)
                LDSM_X4_T(bf[p], Vs_b + (uint32_t)(vrow * 128 +
                                                   (((2 * p + sel_a) ^ lrow) << 4)));
#pragma unroll
            for (int p = 0; p < 4; p++) {
                MMA_F16(o[2 * p],     paf[kc], bf[p][0], bf[p][1]);
                MMA_F16(o[2 * p + 1], paf[kc], bf[p][2], bf[p][3]);
            }
        }
    }

    // Final l reduction (once instead of per-tile)
    float l0v = lp0, l1v = lp1;
    l0v += __shfl_xor_sync(0xffffffffu, l0v, 1);
    l0v += __shfl_xor_sync(0xffffffffu, l0v, 2);
    l1v += __shfl_xor_sync(0xffffffffu, l1v, 1);
    l1v += __shfl_xor_sync(0xffffffffu, l1v, 2);

    // Epilogue: normalize, write g_Oh [B,S,D] fp16
    const float i0 = 1.0f / l0v, i1 = 1.0f / l1v;
    const int b = bh >> 4, h = bh & 15;
    const int row0 = q0 + wq + r, row1 = row0 + 8;
#pragma unroll
    for (int nf = 0; nf < 8; nf++) {
        const int col = h * DH + nf * 8 + 2 * cl;
        __half2 w0 = __floats2half2_rn(o[nf][0] * i0, o[nf][1] * i0);
        __half2 w1 = __floats2half2_rn(o[nf][2] * i1, o[nf][3] * i1);
        *(__half2*)(g_Oh + (size_t)(b * SEQ + row0) * DM + col) = w0;
        *(__half2*)(g_Oh + (size_t)(b * SEQ + row1) * DM + col) = w1;
    }
}

// ============================================================================
// Launch
// ============================================================================
extern "C" void kernel_launch(void* const* d_in, const int* in_sizes, int n_in,
                              void* d_out, int out_size) {
    const float* q  = (const float*)d_in[0];
    const float* kv = (const float*)d_in[1];
    const float* Wq = (const float*)d_in[2];
    const float* Wk = (const float*)d_in[3];
    const float* Wv = (const float*)d_in[4];
    const float* Wo = (const float*)d_in[5];
    float* out = (float*)d_out;

    cudaFuncSetAttribute(qkv_gemm_h, cudaFuncAttributeMaxDynamicSharedMemorySize,
                         GEMM_SMEM_BYTES);
    cudaFuncSetAttribute(proj_gemm_h, cudaFuncAttributeMaxDynamicSharedMemorySize,
                         GEMM_SMEM_BYTES);
    cudaFuncSetAttribute(attn_mma, cudaFuncAttributeMaxDynamicSharedMemorySize,
                         ATTN_SMEM_BYTES);

    f2h_all<<<(2 * N8X + 4 * N8W) / 256, 256>>>(q, kv, Wq, Wk, Wv, Wo);
    qkv_gemm_h<<<dim3(DM / 128, (BATCH * SEQ) / 128, 3), 128, GEMM_SMEM_BYTES>>>(0);
    attn_mma<<<dim3(SEQ / 128, BATCH * NH), 256, ATTN_SMEM_BYTES>>>();
    proj_gemm_h<<<dim3(DM / 128, (BATCH * SEQ) / 128), 128, GEMM_SMEM_BYTES>>>(out);
}